// round 1
// baseline (speedup 1.0000x reference)
#include <cuda_runtime.h>

#define SEQ    2048
#define BATCH  2
#define NROWS  4096            // B*S
#define DIM    2048
#define NMEM   4
#define HDIM   128
#define NHEADS 16
#define KTOT   (NMEM*DIM)

// ---------------- scratch (static device allocations; allocation-free rule) ----
__device__ float g_q  [NROWS*DIM];
__device__ float g_k  [NROWS*DIM];
__device__ float g_v  [NROWS*DIM];
__device__ float g_sig[NROWS*DIM];
__device__ float g_mem[NROWS*DIM];
__device__ float g_loc[NROWS*DIM];
__device__ float g_raw[NMEM*NROWS];
__device__ float g_rel[NMEM*BATCH];
__device__ float g_csc[NMEM*NROWS];

// =====================================================================
// GEMM  C = A * B^T   (A:[M,K] row-major, B:[N,K] row-major) — QKV proj
// 128x128 tile, BK=16, 256 threads, 8x8 microtile
// =====================================================================
__global__ void __launch_bounds__(256) gemm_abt(
    const float* __restrict__ A, const float* __restrict__ B,
    float* __restrict__ C, int M, int N, int K)
{
    __shared__ float As[16][132];
    __shared__ float Bs[16][132];
    const int tid = threadIdx.x;
    const int tx = tid & 15, ty = tid >> 4;
    const int rowBase = blockIdx.y << 7;
    const int colBase = blockIdx.x << 7;
    float acc[8][8];
    #pragma unroll
    for (int i = 0; i < 8; i++)
        #pragma unroll
        for (int j = 0; j < 8; j++) acc[i][j] = 0.f;

    const int lr = tid >> 2;            // 0..63
    const int lc = (tid & 3) << 2;      // 0,4,8,12
    const float* Ap = A + (rowBase + lr) * K + lc;
    const float* Bp = B + (colBase + lr) * K + lc;

    for (int kt = 0; kt < K; kt += 16) {
        float4 a0 = *(const float4*)(Ap + kt);
        float4 a1 = *(const float4*)(Ap + 64 * K + kt);
        float4 b0 = *(const float4*)(Bp + kt);
        float4 b1 = *(const float4*)(Bp + 64 * K + kt);
        As[lc+0][lr]    = a0.x; As[lc+1][lr]    = a0.y; As[lc+2][lr]    = a0.z; As[lc+3][lr]    = a0.w;
        As[lc+0][lr+64] = a1.x; As[lc+1][lr+64] = a1.y; As[lc+2][lr+64] = a1.z; As[lc+3][lr+64] = a1.w;
        Bs[lc+0][lr]    = b0.x; Bs[lc+1][lr]    = b0.y; Bs[lc+2][lr]    = b0.z; Bs[lc+3][lr]    = b0.w;
        Bs[lc+0][lr+64] = b1.x; Bs[lc+1][lr+64] = b1.y; Bs[lc+2][lr+64] = b1.z; Bs[lc+3][lr+64] = b1.w;
        __syncthreads();
        #pragma unroll
        for (int kk = 0; kk < 16; kk++) {
            const float4* Ar = (const float4*)&As[kk][0];
            const float4* Br = (const float4*)&Bs[kk][0];
            float4 va0 = Ar[ty], va1 = Ar[16 + ty];
            float4 vb0 = Br[tx], vb1 = Br[16 + tx];
            float a[8] = {va0.x, va0.y, va0.z, va0.w, va1.x, va1.y, va1.z, va1.w};
            float b[8] = {vb0.x, vb0.y, vb0.z, vb0.w, vb1.x, vb1.y, vb1.z, vb1.w};
            #pragma unroll
            for (int i = 0; i < 8; i++)
                #pragma unroll
                for (int j = 0; j < 8; j++) acc[i][j] += a[i] * b[j];
        }
        __syncthreads();
    }
    #pragma unroll
    for (int i = 0; i < 8; i++) {
        int rr = (i < 4) ? (ty * 4 + i) : (64 + ty * 4 + i - 4);
        float* Cp = C + (size_t)(rowBase + rr) * N + colBase;
        *(float4*)(Cp + tx * 4)      = make_float4(acc[i][0], acc[i][1], acc[i][2], acc[i][3]);
        *(float4*)(Cp + 64 + tx * 4) = make_float4(acc[i][4], acc[i][5], acc[i][6], acc[i][7]);
    }
}

// =====================================================================
// Memory-retrieval GEMM:  C[4096,2048] = A_ext[4096,8192] @ B_ext[8192,2048]
//   A_ext[r, m*2048+d] = csc[m,r] * sigma[r,d]   (generated on the fly)
//   B_ext = memories viewed as [8192, 2048] (N-contiguous)
// =====================================================================
__global__ void __launch_bounds__(256) gemm_mem(
    const float* __restrict__ sig, const float* __restrict__ mem,
    const float* __restrict__ csc, float* __restrict__ C)
{
    __shared__ float As[16][132];
    __shared__ float Bs[16][132];
    const int tid = threadIdx.x;
    const int tx = tid & 15, ty = tid >> 4;
    const int rowBase = blockIdx.y << 7;
    const int colBase = blockIdx.x << 7;
    float acc[8][8];
    #pragma unroll
    for (int i = 0; i < 8; i++)
        #pragma unroll
        for (int j = 0; j < 8; j++) acc[i][j] = 0.f;

    const int lr = tid >> 2;
    const int lc = (tid & 3) << 2;
    const int r0 = rowBase + lr, r1 = r0 + 64;

    for (int kt = 0; kt < KTOT; kt += 16) {
        // A tile (scaled sigma); a 16-wide K tile never crosses a memory boundary
        int kg = kt + lc;
        int mm = kg >> 11;
        int d  = kg & 2047;
        float c0 = csc[mm * NROWS + r0];
        float c1 = csc[mm * NROWS + r1];
        float4 s0 = *(const float4*)(sig + r0 * DIM + d);
        float4 s1 = *(const float4*)(sig + r1 * DIM + d);
        As[lc+0][lr]    = s0.x * c0; As[lc+1][lr]    = s0.y * c0; As[lc+2][lr]    = s0.z * c0; As[lc+3][lr]    = s0.w * c0;
        As[lc+0][lr+64] = s1.x * c1; As[lc+1][lr+64] = s1.y * c1; As[lc+2][lr+64] = s1.z * c1; As[lc+3][lr+64] = s1.w * c1;
        // B tile (memories, row = k index, cols contiguous)
        #pragma unroll
        for (int t = 0; t < 2; t++) {
            int f  = tid + t * 256;
            int br = f >> 5;            // 0..15
            int bc = (f & 31) << 2;     // 0..124
            int kg2 = kt + br;
            int m2 = kg2 >> 11, d2 = kg2 & 2047;
            *(float4*)&Bs[br][bc] = *(const float4*)(mem + (m2 * DIM + d2) * DIM + colBase + bc);
        }
        __syncthreads();
        #pragma unroll
        for (int kk = 0; kk < 16; kk++) {
            const float4* Ar = (const float4*)&As[kk][0];
            const float4* Br = (const float4*)&Bs[kk][0];
            float4 va0 = Ar[ty], va1 = Ar[16 + ty];
            float4 vb0 = Br[tx], vb1 = Br[16 + tx];
            float a[8] = {va0.x, va0.y, va0.z, va0.w, va1.x, va1.y, va1.z, va1.w};
            float b[8] = {vb0.x, vb0.y, vb0.z, vb0.w, vb1.x, vb1.y, vb1.z, vb1.w};
            #pragma unroll
            for (int i = 0; i < 8; i++)
                #pragma unroll
                for (int j = 0; j < 8; j++) acc[i][j] += a[i] * b[j];
        }
        __syncthreads();
    }
    #pragma unroll
    for (int i = 0; i < 8; i++) {
        int rr = (i < 4) ? (ty * 4 + i) : (64 + ty * 4 + i - 4);
        float* Cp = C + (size_t)(rowBase + rr) * DIM + colBase;
        *(float4*)(Cp + tx * 4)      = make_float4(acc[i][0], acc[i][1], acc[i][2], acc[i][3]);
        *(float4*)(Cp + 64 + tx * 4) = make_float4(acc[i][4], acc[i][5], acc[i][6], acc[i][7]);
    }
}

// =====================================================================
// Final GEMM:  out = (g*mem + (1-g)*loc) @ w_o^T   (gate blend fused into A load)
// =====================================================================
__global__ void __launch_bounds__(256) gemm_final(
    const float* __restrict__ memv, const float* __restrict__ locv,
    const float* __restrict__ gate, const float* __restrict__ B,
    float* __restrict__ C, int M, int N, int K)
{
    __shared__ float As[16][132];
    __shared__ float Bs[16][132];
    const int tid = threadIdx.x;
    const int tx = tid & 15, ty = tid >> 4;
    const int rowBase = blockIdx.y << 7;
    const int colBase = blockIdx.x << 7;
    const float g  = 1.f / (1.f + __expf(-gate[0]));
    const float gi = 1.f - g;
    float acc[8][8];
    #pragma unroll
    for (int i = 0; i < 8; i++)
        #pragma unroll
        for (int j = 0; j < 8; j++) acc[i][j] = 0.f;

    const int lr = tid >> 2;
    const int lc = (tid & 3) << 2;
    const float* Mp = memv + (rowBase + lr) * K + lc;
    const float* Lp = locv + (rowBase + lr) * K + lc;
    const float* Bp = B    + (colBase + lr) * K + lc;

    for (int kt = 0; kt < K; kt += 16) {
        float4 m0 = *(const float4*)(Mp + kt);
        float4 m1 = *(const float4*)(Mp + 64 * K + kt);
        float4 l0 = *(const float4*)(Lp + kt);
        float4 l1 = *(const float4*)(Lp + 64 * K + kt);
        float4 b0 = *(const float4*)(Bp + kt);
        float4 b1 = *(const float4*)(Bp + 64 * K + kt);
        As[lc+0][lr]    = g*m0.x + gi*l0.x; As[lc+1][lr]    = g*m0.y + gi*l0.y;
        As[lc+2][lr]    = g*m0.z + gi*l0.z; As[lc+3][lr]    = g*m0.w + gi*l0.w;
        As[lc+0][lr+64] = g*m1.x + gi*l1.x; As[lc+1][lr+64] = g*m1.y + gi*l1.y;
        As[lc+2][lr+64] = g*m1.z + gi*l1.z; As[lc+3][lr+64] = g*m1.w + gi*l1.w;
        Bs[lc+0][lr]    = b0.x; Bs[lc+1][lr]    = b0.y; Bs[lc+2][lr]    = b0.z; Bs[lc+3][lr]    = b0.w;
        Bs[lc+0][lr+64] = b1.x; Bs[lc+1][lr+64] = b1.y; Bs[lc+2][lr+64] = b1.z; Bs[lc+3][lr+64] = b1.w;
        __syncthreads();
        #pragma unroll
        for (int kk = 0; kk < 16; kk++) {
            const float4* Ar = (const float4*)&As[kk][0];
            const float4* Br = (const float4*)&Bs[kk][0];
            float4 va0 = Ar[ty], va1 = Ar[16 + ty];
            float4 vb0 = Br[tx], vb1 = Br[16 + tx];
            float a[8] = {va0.x, va0.y, va0.z, va0.w, va1.x, va1.y, va1.z, va1.w};
            float b[8] = {vb0.x, vb0.y, vb0.z, vb0.w, vb1.x, vb1.y, vb1.z, vb1.w};
            #pragma unroll
            for (int i = 0; i < 8; i++)
                #pragma unroll
                for (int j = 0; j < 8; j++) acc[i][j] += a[i] * b[j];
        }
        __syncthreads();
    }
    #pragma unroll
    for (int i = 0; i < 8; i++) {
        int rr = (i < 4) ? (ty * 4 + i) : (64 + ty * 4 + i - 4);
        float* Cp = C + (size_t)(rowBase + rr) * N + colBase;
        *(float4*)(Cp + tx * 4)      = make_float4(acc[i][0], acc[i][1], acc[i][2], acc[i][3]);
        *(float4*)(Cp + 64 + tx * 4) = make_float4(acc[i][4], acc[i][5], acc[i][6], acc[i][7]);
    }
}

// =====================================================================
// sigma_q = elu(q)+1 ; raw[m,row] = sigma_row . memory_norms[m]
// =====================================================================
__inline__ __device__ float warpReduceSum(float v) {
    #pragma unroll
    for (int o = 16; o > 0; o >>= 1) v += __shfl_down_sync(0xffffffffu, v, o);
    return v;
}

__global__ void __launch_bounds__(256) sigma_raw_kernel(
    const float* __restrict__ q, const float* __restrict__ norms,
    float* __restrict__ sig, float* __restrict__ raw)
{
    const int r = blockIdx.x;
    const int base = r * DIM;
    float a[NMEM] = {0.f, 0.f, 0.f, 0.f};
    for (int c = threadIdx.x * 4; c < DIM; c += 1024) {
        float4 qv = *(const float4*)(q + base + c);
        float4 s;
        s.x = qv.x > 0.f ? qv.x + 1.f : __expf(qv.x);
        s.y = qv.y > 0.f ? qv.y + 1.f : __expf(qv.y);
        s.z = qv.z > 0.f ? qv.z + 1.f : __expf(qv.z);
        s.w = qv.w > 0.f ? qv.w + 1.f : __expf(qv.w);
        *(float4*)(sig + base + c) = s;
        #pragma unroll
        for (int m = 0; m < NMEM; m++) {
            float4 nv = *(const float4*)(norms + m * DIM + c);
            a[m] += s.x * nv.x + s.y * nv.y + s.z * nv.z + s.w * nv.w;
        }
    }
    __shared__ float red[NMEM][8];
    const int lane = threadIdx.x & 31, wid = threadIdx.x >> 5;
    #pragma unroll
    for (int m = 0; m < NMEM; m++) a[m] = warpReduceSum(a[m]);
    if (lane == 0)
        #pragma unroll
        for (int m = 0; m < NMEM; m++) red[m][wid] = a[m];
    __syncthreads();
    if (wid == 0) {
        #pragma unroll
        for (int m = 0; m < NMEM; m++) {
            float v = (lane < 8) ? red[m][lane] : 0.f;
            v = warpReduceSum(v);
            if (lane == 0) raw[m * NROWS + r] = v;
        }
    }
}

// rel[m,b] = mean_s raw[m, b*SEQ + s]
__global__ void __launch_bounds__(256) rel_kernel(
    const float* __restrict__ raw, float* __restrict__ rel)
{
    const int m = blockIdx.x >> 1, b = blockIdx.x & 1;
    float acc = 0.f;
    for (int s = threadIdx.x; s < SEQ; s += 256) acc += raw[m * NROWS + b * SEQ + s];
    __shared__ float red[8];
    const int lane = threadIdx.x & 31, wid = threadIdx.x >> 5;
    acc = warpReduceSum(acc);
    if (lane == 0) red[wid] = acc;
    __syncthreads();
    if (threadIdx.x == 0) {
        float t = 0.f;
        #pragma unroll
        for (int w = 0; w < 8; w++) t += red[w];
        rel[m * BATCH + b] = t / (float)SEQ;
    }
}

// csc[m,row] = softmax_m(rel)[m,b] / max(raw[m,row], 1e-6)
__global__ void __launch_bounds__(256) cscale_kernel(
    const float* __restrict__ raw, const float* __restrict__ rel,
    float* __restrict__ csc)
{
    const int r = blockIdx.x * 256 + threadIdx.x;
    if (r >= NROWS) return;
    const int b = r >> 11;
    float e[NMEM];
    #pragma unroll
    for (int m = 0; m < NMEM; m++) e[m] = rel[m * BATCH + b];
    float mx = fmaxf(fmaxf(e[0], e[1]), fmaxf(e[2], e[3]));
    float w[NMEM], sum = 0.f;
    #pragma unroll
    for (int m = 0; m < NMEM; m++) { w[m] = __expf(e[m] - mx); sum += w[m]; }
    const float inv = 1.f / sum;
    #pragma unroll
    for (int m = 0; m < NMEM; m++)
        csc[m * NROWS + r] = w[m] * inv / fmaxf(raw[m * NROWS + r], 1e-6f);
}

// =====================================================================
// Flash attention (causal), fp32. Br=Bc=64, hd=128. One block per (qtile, b*h)
// =====================================================================
#define FLASH_SMEM ((3 * 64 * 132 + 64 * 68) * 4)

__global__ void __launch_bounds__(256) flash_attn(
    const float* __restrict__ Q, const float* __restrict__ K,
    const float* __restrict__ V, float* __restrict__ O)
{
    extern __shared__ float sm[];
    float* Qs = sm;                 // 64 x 132
    float* Ks = Qs + 64 * 132;      // 64 x 132
    float* Vs = Ks + 64 * 132;      // 64 x 132
    float* Ps = Vs + 64 * 132;      // 64 x 68
    const int tid = threadIdx.x;
    const int tx = tid & 15, ty = tid >> 4;
    const int qb = blockIdx.x;              // q tile (0..31)
    const int bh = blockIdx.y;              // 0..31
    const int b = bh >> 4, h = bh & 15;
    const float scale = 0.08838834764831845f;   // 1/sqrt(128)

    const float* Qg = Q + (size_t)(b * SEQ + qb * 64) * DIM + h * HDIM;
    #pragma unroll
    for (int t = 0; t < 8; t++) {
        int f = tid + t * 256;
        int r = f >> 5, c = (f & 31) << 2;
        *(float4*)&Qs[r * 132 + c] = *(const float4*)(Qg + r * DIM + c);
    }
    float m_i[4], l_i[4], o[4][8];
    #pragma unroll
    for (int i = 0; i < 4; i++) {
        m_i[i] = -1e30f; l_i[i] = 0.f;
        #pragma unroll
        for (int j = 0; j < 8; j++) o[i][j] = 0.f;
    }

    for (int kt = 0; kt <= qb; kt++) {
        const float* Kg = K + (size_t)(b * SEQ + kt * 64) * DIM + h * HDIM;
        const float* Vg = V + (size_t)(b * SEQ + kt * 64) * DIM + h * HDIM;
        #pragma unroll
        for (int t = 0; t < 8; t++) {
            int f = tid + t * 256;
            int r = f >> 5, c = (f & 31) << 2;
            *(float4*)&Ks[r * 132 + c] = *(const float4*)(Kg + r * DIM + c);
            *(float4*)&Vs[r * 132 + c] = *(const float4*)(Vg + r * DIM + c);
        }
        __syncthreads();

        // S = Q K^T  (thread: rows ty*4+i, cols 16*j+tx)
        float s[4][4];
        #pragma unroll
        for (int i = 0; i < 4; i++)
            #pragma unroll
            for (int j = 0; j < 4; j++) s[i][j] = 0.f;
        #pragma unroll 4
        for (int kk = 0; kk < HDIM; kk += 4) {
            float4 q4[4], k4[4];
            #pragma unroll
            for (int i = 0; i < 4; i++) q4[i] = *(const float4*)&Qs[(ty * 4 + i) * 132 + kk];
            #pragma unroll
            for (int j = 0; j < 4; j++) k4[j] = *(const float4*)&Ks[(16 * j + tx) * 132 + kk];
            #pragma unroll
            for (int i = 0; i < 4; i++)
                #pragma unroll
                for (int j = 0; j < 4; j++)
                    s[i][j] += q4[i].x * k4[j].x + q4[i].y * k4[j].y
                             + q4[i].z * k4[j].z + q4[i].w * k4[j].w;
        }
        #pragma unroll
        for (int i = 0; i < 4; i++)
            #pragma unroll
            for (int j = 0; j < 4; j++) s[i][j] *= scale;
        if (kt == qb) {
            #pragma unroll
            for (int i = 0; i < 4; i++)
                #pragma unroll
                for (int j = 0; j < 4; j++)
                    if (16 * j + tx > ty * 4 + i) s[i][j] = -1e30f;
        }

        // online softmax per row (reduce across the 16 tx lanes)
        #pragma unroll
        for (int i = 0; i < 4; i++) {
            float rm = fmaxf(fmaxf(s[i][0], s[i][1]), fmaxf(s[i][2], s[i][3]));
            #pragma unroll
            for (int off = 1; off < 16; off <<= 1)
                rm = fmaxf(rm, __shfl_xor_sync(0xffffffffu, rm, off));
            float mn = fmaxf(m_i[i], rm);
            float corr = __expf(m_i[i] - mn);
            float rs = 0.f;
            #pragma unroll
            for (int j = 0; j < 4; j++) {
                float p = __expf(s[i][j] - mn);
                Ps[(ty * 4 + i) * 68 + 16 * j + tx] = p;
                rs += p;
            }
            #pragma unroll
            for (int off = 1; off < 16; off <<= 1)
                rs += __shfl_xor_sync(0xffffffffu, rs, off);
            l_i[i] = l_i[i] * corr + rs;
            m_i[i] = mn;
            #pragma unroll
            for (int jj = 0; jj < 8; jj++) o[i][jj] *= corr;
        }
        __syncthreads();

        // O += P V   (thread: rows ty*4+i, cols tx*4.. and 64+tx*4..)
        for (int c = 0; c < 64; c += 4) {
            float4 pr[4];
            #pragma unroll
            for (int i = 0; i < 4; i++) pr[i] = *(const float4*)&Ps[(ty * 4 + i) * 68 + c];
            #pragma unroll
            for (int cc = 0; cc < 4; cc++) {
                float4 va = *(const float4*)&Vs[(c + cc) * 132 + tx * 4];
                float4 vb = *(const float4*)&Vs[(c + cc) * 132 + 64 + tx * 4];
                #pragma unroll
                for (int i = 0; i < 4; i++) {
                    float pv = (cc == 0) ? pr[i].x : (cc == 1) ? pr[i].y : (cc == 2) ? pr[i].z : pr[i].w;
                    o[i][0] += pv * va.x; o[i][1] += pv * va.y; o[i][2] += pv * va.z; o[i][3] += pv * va.w;
                    o[i][4] += pv * vb.x; o[i][5] += pv * vb.y; o[i][6] += pv * vb.z; o[i][7] += pv * vb.w;
                }
            }
        }
        __syncthreads();
    }

    #pragma unroll
    for (int i = 0; i < 4; i++) {
        float inv = 1.f / l_i[i];
        float* Op = O + (size_t)(b * SEQ + qb * 64 + ty * 4 + i) * DIM + h * HDIM;
        *(float4*)(Op + tx * 4)      = make_float4(o[i][0]*inv, o[i][1]*inv, o[i][2]*inv, o[i][3]*inv);
        *(float4*)(Op + 64 + tx * 4) = make_float4(o[i][4]*inv, o[i][5]*inv, o[i][6]*inv, o[i][7]*inv);
    }
}

// =====================================================================
extern "C" void kernel_launch(void* const* d_in, const int* in_sizes, int n_in,
                              void* d_out, int out_size)
{
    const float* x        = (const float*)d_in[0];
    const float* w_q      = (const float*)d_in[1];
    const float* w_k      = (const float*)d_in[2];
    const float* w_v      = (const float*)d_in[3];
    const float* w_o      = (const float*)d_in[4];
    const float* gate     = (const float*)d_in[5];
    const float* memories = (const float*)d_in[6];
    const float* mnorms   = (const float*)d_in[7];
    float* out = (float*)d_out;

    float *q, *k, *v, *sig, *memo, *loc, *raw, *rel, *csc;
    cudaGetSymbolAddress((void**)&q,    g_q);
    cudaGetSymbolAddress((void**)&k,    g_k);
    cudaGetSymbolAddress((void**)&v,    g_v);
    cudaGetSymbolAddress((void**)&sig,  g_sig);
    cudaGetSymbolAddress((void**)&memo, g_mem);
    cudaGetSymbolAddress((void**)&loc,  g_loc);
    cudaGetSymbolAddress((void**)&raw,  g_raw);
    cudaGetSymbolAddress((void**)&rel,  g_rel);
    cudaGetSymbolAddress((void**)&csc,  g_csc);

    dim3 gg(DIM / 128, NROWS / 128);   // (16, 32)

    gemm_abt<<<gg, 256>>>(x, w_q, q, NROWS, DIM, DIM);
    gemm_abt<<<gg, 256>>>(x, w_k, k, NROWS, DIM, DIM);
    gemm_abt<<<gg, 256>>>(x, w_v, v, NROWS, DIM, DIM);

    sigma_raw_kernel<<<NROWS, 256>>>(q, mnorms, sig, raw);
    rel_kernel<<<NMEM * BATCH, 256>>>(raw, rel);
    cscale_kernel<<<NROWS / 256, 256>>>(raw, rel, csc);
    gemm_mem<<<gg, 256>>>(sig, memories, csc, memo);

    cudaFuncSetAttribute(flash_attn, cudaFuncAttributeMaxDynamicSharedMemorySize, FLASH_SMEM);
    flash_attn<<<dim3(SEQ / 64, BATCH * NHEADS), 256, FLASH_SMEM>>>(q, k, v, loc);

    gemm_final<<<gg, 256>>>(memo, loc, gate, w_o, out, NROWS, DIM, DIM);
}

// round 3
// speedup vs baseline: 1.1811x; 1.1811x over previous
#include <cuda_runtime.h>
#include <cstdint>

#define SEQ    2048
#define BATCH  2
#define NROWS  4096
#define DIM    2048
#define NMEM   4
#define HDIM   128
#define NHEADS 16
#define KTOT   (NMEM*DIM)

// ---------------- scratch ----------------
__device__ float g_q  [NROWS*DIM];
__device__ float g_k  [NROWS*DIM];
__device__ float g_v  [NROWS*DIM];
__device__ float g_sig[NROWS*DIM];   // sigma; later reused as blend buffer
__device__ float g_mem[NROWS*DIM];
__device__ float g_loc[NROWS*DIM];
__device__ float g_bt [DIM*KTOT];    // transposed memories [E=2048][K=8192]
__device__ float g_raw[NMEM*NROWS];
__device__ float g_rel[NMEM*BATCH];
__device__ float g_csc[NMEM*NROWS];

// ---------------- mma.sync tf32 ----------------
#define MMA_TF32(c, a0, a1, a2, a3, b0, b1) \
    asm volatile("mma.sync.aligned.m16n8k8.row.col.f32.tf32.tf32.f32 " \
        "{%0,%1,%2,%3}, {%4,%5,%6,%7}, {%8,%9}, {%0,%1,%2,%3};" \
        : "+f"((c)[0]), "+f"((c)[1]), "+f"((c)[2]), "+f"((c)[3]) \
        : "r"(a0), "r"(a1), "r"(a2), "r"(a3), "r"(b0), "r"(b1))

__device__ __forceinline__ uint32_t f2b(float x) { return __float_as_uint(x); }
__device__ __forceinline__ float tf32_hi(float x) {
    return __uint_as_float(__float_as_uint(x) & 0xFFFFE000u);
}

#define APAD 36
#define BPAD 136

// =====================================================================
// 3xTF32 split GEMM (fp32-accurate): C[M,N] = A[M,K] * B[N,K]^T
// 128x128 tile, BK=32, 256 threads (8 warps, 4x2), warp tile 32x64.
// =====================================================================
__global__ void __launch_bounds__(256) gemm_mma3(
    const float* __restrict__ A, const float* __restrict__ B,
    float* __restrict__ C, int M, int N, int K)
{
    extern __shared__ float sm[];
    float* Ah = sm;                    // [128][APAD]
    float* Al = Ah + 128 * APAD;
    float* Bh = Al + 128 * APAD;       // [32][BPAD] (k-major)
    float* Bl = Bh + 32 * BPAD;

    const int tid = threadIdx.x;
    const int lane = tid & 31, wid = tid >> 5;
    const int wm = wid & 3, wn = wid >> 2;
    const int m0 = wm * 32, n0 = wn * 64;
    const int row = lane >> 2, col = lane & 3;
    const int rowBase = blockIdx.y << 7;
    const int colBase = blockIdx.x << 7;

    const int lm = tid & 127, lkq = tid >> 7;   // loader: row 0..127, k-half 0/1

    float c[2][8][4];
    #pragma unroll
    for (int i = 0; i < 2; i++)
        #pragma unroll
        for (int j = 0; j < 8; j++)
            #pragma unroll
            for (int t = 0; t < 4; t++) c[i][j][t] = 0.f;

    const int nt = K >> 5;
    for (int kt = 0; kt < nt; kt++) {
        // global loads into registers
        float4 av[4], bv[4];
        const float* Ag = A + (size_t)(rowBase + lm) * K + (kt << 5) + (lkq << 4);
        const float* Bg = B + (size_t)(colBase + lm) * K + (kt << 5) + (lkq << 4);
        #pragma unroll
        for (int u = 0; u < 4; u++) { av[u] = *(const float4*)(Ag + 4 * u); bv[u] = *(const float4*)(Bg + 4 * u); }
        __syncthreads();
        #pragma unroll
        for (int u = 0; u < 4; u++) {
            int kk = (lkq << 4) + (u << 2);
            float4 h = make_float4(tf32_hi(av[u].x), tf32_hi(av[u].y), tf32_hi(av[u].z), tf32_hi(av[u].w));
            *(float4*)&Ah[lm * APAD + kk] = h;
            *(float4*)&Al[lm * APAD + kk] = make_float4(av[u].x - h.x, av[u].y - h.y, av[u].z - h.z, av[u].w - h.w);
            #pragma unroll
            for (int t = 0; t < 4; t++) {
                float bvv = (t == 0) ? bv[u].x : (t == 1) ? bv[u].y : (t == 2) ? bv[u].z : bv[u].w;
                float bh = tf32_hi(bvv);
                Bh[(kk + t) * BPAD + lm] = bh;
                Bl[(kk + t) * BPAD + lm] = bvv - bh;
            }
        }
        __syncthreads();

        #pragma unroll
        for (int k8 = 0; k8 < 4; k8++) {
            const int kb = k8 << 3;
            uint32_t ah[2][4], al[2][4];
            #pragma unroll
            for (int i = 0; i < 2; i++) {
                int mr = m0 + i * 16 + row;
                ah[i][0] = f2b(Ah[mr * APAD + kb + col]);
                ah[i][1] = f2b(Ah[(mr + 8) * APAD + kb + col]);
                ah[i][2] = f2b(Ah[mr * APAD + kb + col + 4]);
                ah[i][3] = f2b(Ah[(mr + 8) * APAD + kb + col + 4]);
                al[i][0] = f2b(Al[mr * APAD + kb + col]);
                al[i][1] = f2b(Al[(mr + 8) * APAD + kb + col]);
                al[i][2] = f2b(Al[mr * APAD + kb + col + 4]);
                al[i][3] = f2b(Al[(mr + 8) * APAD + kb + col + 4]);
            }
            #pragma unroll
            for (int j = 0; j < 8; j++) {
                int nn = n0 + j * 8 + row;
                int kr = kb + col;
                uint32_t bh0 = f2b(Bh[kr * BPAD + nn]);
                uint32_t bh1 = f2b(Bh[(kr + 4) * BPAD + nn]);
                uint32_t bl0 = f2b(Bl[kr * BPAD + nn]);
                uint32_t bl1 = f2b(Bl[(kr + 4) * BPAD + nn]);
                #pragma unroll
                for (int i = 0; i < 2; i++) {
                    MMA_TF32(c[i][j], ah[i][0], ah[i][1], ah[i][2], ah[i][3], bh0, bh1);
                    MMA_TF32(c[i][j], al[i][0], al[i][1], al[i][2], al[i][3], bh0, bh1);
                    MMA_TF32(c[i][j], ah[i][0], ah[i][1], ah[i][2], ah[i][3], bl0, bl1);
                }
            }
        }
    }

    #pragma unroll
    for (int i = 0; i < 2; i++) {
        int r0 = rowBase + m0 + i * 16 + row;
        #pragma unroll
        for (int j = 0; j < 8; j++) {
            int cc = colBase + n0 + j * 8 + 2 * col;
            *(float2*)(C + (size_t)r0 * N + cc)       = make_float2(c[i][j][0], c[i][j][1]);
            *(float2*)(C + (size_t)(r0 + 8) * N + cc) = make_float2(c[i][j][2], c[i][j][3]);
        }
    }
}

// =====================================================================
// Single-pass tf32 GEMM for memory retrieval:
// C[4096,2048] = A_ext[4096,8192] @ B_ext^T, A_ext[r,k] = csc[k>>11, r]*sigma[r, k&2047]
// B = bt [2048][8192] (row n, col k).
// =====================================================================
__global__ void __launch_bounds__(256) gemm_mma_mem(
    const float* __restrict__ sig, const float* __restrict__ bt,
    const float* __restrict__ csc, float* __restrict__ C)
{
    extern __shared__ float sm[];
    float* As = sm;                    // [128][APAD]
    float* Bs = As + 128 * APAD;       // [32][BPAD]

    const int tid = threadIdx.x;
    const int lane = tid & 31, wid = tid >> 5;
    const int wm = wid & 3, wn = wid >> 2;
    const int m0 = wm * 32, n0 = wn * 64;
    const int row = lane >> 2, col = lane & 3;
    const int rowBase = blockIdx.y << 7;
    const int colBase = blockIdx.x << 7;
    const int lm = tid & 127, lkq = tid >> 7;

    float c[2][8][4];
    #pragma unroll
    for (int i = 0; i < 2; i++)
        #pragma unroll
        for (int j = 0; j < 8; j++)
            #pragma unroll
            for (int t = 0; t < 4; t++) c[i][j][t] = 0.f;

    for (int kt = 0; kt < (KTOT >> 5); kt++) {
        const int kg = kt << 5;
        const int mi = kg >> 11;              // memory index, constant per tile
        const int d0 = kg & 2047;
        float sc = csc[mi * NROWS + rowBase + lm];
        float4 av[4], bv[4];
        const float* Ag = sig + (size_t)(rowBase + lm) * DIM + d0 + (lkq << 4);
        const float* Bg = bt + (size_t)(colBase + lm) * KTOT + kg + (lkq << 4);
        #pragma unroll
        for (int u = 0; u < 4; u++) { av[u] = *(const float4*)(Ag + 4 * u); bv[u] = *(const float4*)(Bg + 4 * u); }
        __syncthreads();
        #pragma unroll
        for (int u = 0; u < 4; u++) {
            int kk = (lkq << 4) + (u << 2);
            *(float4*)&As[lm * APAD + kk] = make_float4(av[u].x * sc, av[u].y * sc, av[u].z * sc, av[u].w * sc);
            Bs[(kk + 0) * BPAD + lm] = bv[u].x;
            Bs[(kk + 1) * BPAD + lm] = bv[u].y;
            Bs[(kk + 2) * BPAD + lm] = bv[u].z;
            Bs[(kk + 3) * BPAD + lm] = bv[u].w;
        }
        __syncthreads();

        #pragma unroll
        for (int k8 = 0; k8 < 4; k8++) {
            const int kb = k8 << 3;
            uint32_t a[2][4];
            #pragma unroll
            for (int i = 0; i < 2; i++) {
                int mr = m0 + i * 16 + row;
                a[i][0] = f2b(As[mr * APAD + kb + col]);
                a[i][1] = f2b(As[(mr + 8) * APAD + kb + col]);
                a[i][2] = f2b(As[mr * APAD + kb + col + 4]);
                a[i][3] = f2b(As[(mr + 8) * APAD + kb + col + 4]);
            }
            #pragma unroll
            for (int j = 0; j < 8; j++) {
                int nn = n0 + j * 8 + row;
                int kr = kb + col;
                uint32_t b0 = f2b(Bs[kr * BPAD + nn]);
                uint32_t b1 = f2b(Bs[(kr + 4) * BPAD + nn]);
                #pragma unroll
                for (int i = 0; i < 2; i++)
                    MMA_TF32(c[i][j], a[i][0], a[i][1], a[i][2], a[i][3], b0, b1);
            }
        }
    }

    #pragma unroll
    for (int i = 0; i < 2; i++) {
        int r0 = rowBase + m0 + i * 16 + row;
        #pragma unroll
        for (int j = 0; j < 8; j++) {
            int cc = colBase + n0 + j * 8 + 2 * col;
            *(float2*)(C + (size_t)r0 * DIM + cc)       = make_float2(c[i][j][0], c[i][j][1]);
            *(float2*)(C + (size_t)(r0 + 8) * DIM + cc) = make_float2(c[i][j][2], c[i][j][3]);
        }
    }
}

// =====================================================================
// memories [M,D,E] -> bt [E][m*D+d]
// =====================================================================
__global__ void transpose_mem(const float* __restrict__ mem, float* __restrict__ bt)
{
    __shared__ float t[32][33];
    const int m = blockIdx.z;
    const int d0 = blockIdx.x << 5, e0 = blockIdx.y << 5;
    const float* src = mem + ((size_t)m * DIM + d0) * DIM + e0;
    for (int i = threadIdx.y; i < 32; i += 8)
        t[i][threadIdx.x] = src[(size_t)i * DIM + threadIdx.x];
    __syncthreads();
    float* dst = bt + (size_t)e0 * KTOT + m * DIM + d0;
    for (int i = threadIdx.y; i < 32; i += 8)
        dst[(size_t)i * KTOT + threadIdx.x] = t[threadIdx.x][i];
}

// =====================================================================
// sigma / raw / rel / cscale / blend
// =====================================================================
__inline__ __device__ float warpReduceSum(float v) {
    #pragma unroll
    for (int o = 16; o > 0; o >>= 1) v += __shfl_down_sync(0xffffffffu, v, o);
    return v;
}

__global__ void __launch_bounds__(256) sigma_raw_kernel(
    const float* __restrict__ q, const float* __restrict__ norms,
    float* __restrict__ sig, float* __restrict__ raw)
{
    const int r = blockIdx.x;
    const int base = r * DIM;
    float a[NMEM] = {0.f, 0.f, 0.f, 0.f};
    for (int c = threadIdx.x * 4; c < DIM; c += 1024) {
        float4 qv = *(const float4*)(q + base + c);
        float4 s;
        s.x = qv.x > 0.f ? qv.x + 1.f : __expf(qv.x);
        s.y = qv.y > 0.f ? qv.y + 1.f : __expf(qv.y);
        s.z = qv.z > 0.f ? qv.z + 1.f : __expf(qv.z);
        s.w = qv.w > 0.f ? qv.w + 1.f : __expf(qv.w);
        *(float4*)(sig + base + c) = s;
        #pragma unroll
        for (int m = 0; m < NMEM; m++) {
            float4 nv = *(const float4*)(norms + m * DIM + c);
            a[m] += s.x * nv.x + s.y * nv.y + s.z * nv.z + s.w * nv.w;
        }
    }
    __shared__ float red[NMEM][8];
    const int lane = threadIdx.x & 31, wid = threadIdx.x >> 5;
    #pragma unroll
    for (int m = 0; m < NMEM; m++) a[m] = warpReduceSum(a[m]);
    if (lane == 0)
        #pragma unroll
        for (int m = 0; m < NMEM; m++) red[m][wid] = a[m];
    __syncthreads();
    if (wid == 0) {
        #pragma unroll
        for (int m = 0; m < NMEM; m++) {
            float v = (lane < 8) ? red[m][lane] : 0.f;
            v = warpReduceSum(v);
            if (lane == 0) raw[m * NROWS + r] = v;
        }
    }
}

__global__ void __launch_bounds__(256) rel_kernel(
    const float* __restrict__ raw, float* __restrict__ rel)
{
    const int m = blockIdx.x >> 1, b = blockIdx.x & 1;
    float acc = 0.f;
    for (int s = threadIdx.x; s < SEQ; s += 256) acc += raw[m * NROWS + b * SEQ + s];
    __shared__ float red[8];
    const int lane = threadIdx.x & 31, wid = threadIdx.x >> 5;
    acc = warpReduceSum(acc);
    if (lane == 0) red[wid] = acc;
    __syncthreads();
    if (threadIdx.x == 0) {
        float t = 0.f;
        #pragma unroll
        for (int w = 0; w < 8; w++) t += red[w];
        rel[m * BATCH + b] = t / (float)SEQ;
    }
}

__global__ void __launch_bounds__(256) cscale_kernel(
    const float* __restrict__ raw, const float* __restrict__ rel,
    float* __restrict__ csc)
{
    const int r = blockIdx.x * 256 + threadIdx.x;
    if (r >= NROWS) return;
    const int b = r >> 11;
    float e[NMEM];
    #pragma unroll
    for (int m = 0; m < NMEM; m++) e[m] = rel[m * BATCH + b];
    float mx = fmaxf(fmaxf(e[0], e[1]), fmaxf(e[2], e[3]));
    float w[NMEM], sum = 0.f;
    #pragma unroll
    for (int m = 0; m < NMEM; m++) { w[m] = __expf(e[m] - mx); sum += w[m]; }
    const float inv = 1.f / sum;
    #pragma unroll
    for (int m = 0; m < NMEM; m++)
        csc[m * NROWS + r] = w[m] * inv / fmaxf(raw[m * NROWS + r], 1e-6f);
}

__global__ void __launch_bounds__(256) blend_kernel(
    const float* __restrict__ mem, const float* __restrict__ loc,
    const float* __restrict__ gate, float* __restrict__ bl)
{
    const int i = blockIdx.x * 256 + threadIdx.x;
    const float g = 1.f / (1.f + __expf(-gate[0]));
    const float gi = 1.f - g;
    float4 m = ((const float4*)mem)[i], l = ((const float4*)loc)[i];
    ((float4*)bl)[i] = make_float4(g*m.x + gi*l.x, g*m.y + gi*l.y,
                                   g*m.z + gi*l.z, g*m.w + gi*l.w);
}

// =====================================================================
// Flash attention (causal), fp32 (known good from round 1)
// =====================================================================
#define FLASH_SMEM ((3 * 64 * 132 + 64 * 68) * 4)

__global__ void __launch_bounds__(256) flash_attn(
    const float* __restrict__ Q, const float* __restrict__ K,
    const float* __restrict__ V, float* __restrict__ O)
{
    extern __shared__ float smf[];
    float* Qs = smf;
    float* Ks = Qs + 64 * 132;
    float* Vs = Ks + 64 * 132;
    float* Ps = Vs + 64 * 132;
    const int tid = threadIdx.x;
    const int tx = tid & 15, ty = tid >> 4;
    const int qb = blockIdx.x;
    const int bh = blockIdx.y;
    const int b = bh >> 4, h = bh & 15;
    const float scale = 0.08838834764831845f;

    const float* Qg = Q + (size_t)(b * SEQ + qb * 64) * DIM + h * HDIM;
    #pragma unroll
    for (int t = 0; t < 8; t++) {
        int f = tid + t * 256;
        int r = f >> 5, c = (f & 31) << 2;
        *(float4*)&Qs[r * 132 + c] = *(const float4*)(Qg + r * DIM + c);
    }
    float m_i[4], l_i[4], o[4][8];
    #pragma unroll
    for (int i = 0; i < 4; i++) {
        m_i[i] = -1e30f; l_i[i] = 0.f;
        #pragma unroll
        for (int j = 0; j < 8; j++) o[i][j] = 0.f;
    }

    for (int kt = 0; kt <= qb; kt++) {
        const float* Kg = K + (size_t)(b * SEQ + kt * 64) * DIM + h * HDIM;
        const float* Vg = V + (size_t)(b * SEQ + kt * 64) * DIM + h * HDIM;
        #pragma unroll
        for (int t = 0; t < 8; t++) {
            int f = tid + t * 256;
            int r = f >> 5, c = (f & 31) << 2;
            *(float4*)&Ks[r * 132 + c] = *(const float4*)(Kg + r * DIM + c);
            *(float4*)&Vs[r * 132 + c] = *(const float4*)(Vg + r * DIM + c);
        }
        __syncthreads();

        float s[4][4];
        #pragma unroll
        for (int i = 0; i < 4; i++)
            #pragma unroll
            for (int j = 0; j < 4; j++) s[i][j] = 0.f;
        #pragma unroll 4
        for (int kk = 0; kk < HDIM; kk += 4) {
            float4 q4[4], k4[4];
            #pragma unroll
            for (int i = 0; i < 4; i++) q4[i] = *(const float4*)&Qs[(ty * 4 + i) * 132 + kk];
            #pragma unroll
            for (int j = 0; j < 4; j++) k4[j] = *(const float4*)&Ks[(16 * j + tx) * 132 + kk];
            #pragma unroll
            for (int i = 0; i < 4; i++)
                #pragma unroll
                for (int j = 0; j < 4; j++)
                    s[i][j] += q4[i].x * k4[j].x + q4[i].y * k4[j].y
                             + q4[i].z * k4[j].z + q4[i].w * k4[j].w;
        }
        #pragma unroll
        for (int i = 0; i < 4; i++)
            #pragma unroll
            for (int j = 0; j < 4; j++) s[i][j] *= scale;
        if (kt == qb) {
            #pragma unroll
            for (int i = 0; i < 4; i++)
                #pragma unroll
                for (int j = 0; j < 4; j++)
                    if (16 * j + tx > ty * 4 + i) s[i][j] = -1e30f;
        }

        #pragma unroll
        for (int i = 0; i < 4; i++) {
            float rm = fmaxf(fmaxf(s[i][0], s[i][1]), fmaxf(s[i][2], s[i][3]));
            #pragma unroll
            for (int off = 1; off < 16; off <<= 1)
                rm = fmaxf(rm, __shfl_xor_sync(0xffffffffu, rm, off));
            float mn = fmaxf(m_i[i], rm);
            float corr = __expf(m_i[i] - mn);
            float rs = 0.f;
            #pragma unroll
            for (int j = 0; j < 4; j++) {
                float p = __expf(s[i][j] - mn);
                Ps[(ty * 4 + i) * 68 + 16 * j + tx] = p;
                rs += p;
            }
            #pragma unroll
            for (int off = 1; off < 16; off <<= 1)
                rs += __shfl_xor_sync(0xffffffffu, rs, off);
            l_i[i] = l_i[i] * corr + rs;
            m_i[i] = mn;
            #pragma unroll
            for (int jj = 0; jj < 8; jj++) o[i][jj] *= corr;
        }
        __syncthreads();

        for (int c = 0; c < 64; c += 4) {
            float4 pr[4];
            #pragma unroll
            for (int i = 0; i < 4; i++) pr[i] = *(const float4*)&Ps[(ty * 4 + i) * 68 + c];
            #pragma unroll
            for (int cc = 0; cc < 4; cc++) {
                float4 va = *(const float4*)&Vs[(c + cc) * 132 + tx * 4];
                float4 vb = *(const float4*)&Vs[(c + cc) * 132 + 64 + tx * 4];
                #pragma unroll
                for (int i = 0; i < 4; i++) {
                    float pv = (cc == 0) ? pr[i].x : (cc == 1) ? pr[i].y : (cc == 2) ? pr[i].z : pr[i].w;
                    o[i][0] += pv * va.x; o[i][1] += pv * va.y; o[i][2] += pv * va.z; o[i][3] += pv * va.w;
                    o[i][4] += pv * vb.x; o[i][5] += pv * vb.y; o[i][6] += pv * vb.z; o[i][7] += pv * vb.w;
                }
            }
        }
        __syncthreads();
    }

    #pragma unroll
    for (int i = 0; i < 4; i++) {
        float inv = 1.f / l_i[i];
        float* Op = O + (size_t)(b * SEQ + qb * 64 + ty * 4 + i) * DIM + h * HDIM;
        *(float4*)(Op + tx * 4)      = make_float4(o[i][0]*inv, o[i][1]*inv, o[i][2]*inv, o[i][3]*inv);
        *(float4*)(Op + 64 + tx * 4) = make_float4(o[i][4]*inv, o[i][5]*inv, o[i][6]*inv, o[i][7]*inv);
    }
}

// =====================================================================
#define SMEM_G3  ((128*APAD*2 + 32*BPAD*2) * 4)
#define SMEM_GM  ((128*APAD + 32*BPAD) * 4)

extern "C" void kernel_launch(void* const* d_in, const int* in_sizes, int n_in,
                              void* d_out, int out_size)
{
    const float* x        = (const float*)d_in[0];
    const float* w_q      = (const float*)d_in[1];
    const float* w_k      = (const float*)d_in[2];
    const float* w_v      = (const float*)d_in[3];
    const float* w_o      = (const float*)d_in[4];
    const float* gate     = (const float*)d_in[5];
    const float* memories = (const float*)d_in[6];
    const float* mnorms   = (const float*)d_in[7];
    float* out = (float*)d_out;

    float *q, *k, *v, *sig, *memo, *loc, *bt, *raw, *rel, *csc;
    cudaGetSymbolAddress((void**)&q,    g_q);
    cudaGetSymbolAddress((void**)&k,    g_k);
    cudaGetSymbolAddress((void**)&v,    g_v);
    cudaGetSymbolAddress((void**)&sig,  g_sig);
    cudaGetSymbolAddress((void**)&memo, g_mem);
    cudaGetSymbolAddress((void**)&loc,  g_loc);
    cudaGetSymbolAddress((void**)&bt,   g_bt);
    cudaGetSymbolAddress((void**)&raw,  g_raw);
    cudaGetSymbolAddress((void**)&rel,  g_rel);
    cudaGetSymbolAddress((void**)&csc,  g_csc);

    cudaFuncSetAttribute(gemm_mma3,    cudaFuncAttributeMaxDynamicSharedMemorySize, SMEM_G3);
    cudaFuncSetAttribute(gemm_mma_mem, cudaFuncAttributeMaxDynamicSharedMemorySize, SMEM_GM);
    cudaFuncSetAttribute(flash_attn,   cudaFuncAttributeMaxDynamicSharedMemorySize, FLASH_SMEM);

    dim3 gg(DIM / 128, NROWS / 128);   // (16, 32)

    transpose_mem<<<dim3(DIM / 32, DIM / 32, NMEM), dim3(32, 8)>>>(memories, bt);

    gemm_mma3<<<gg, 256, SMEM_G3>>>(x, w_q, q, NROWS, DIM, DIM);
    gemm_mma3<<<gg, 256, SMEM_G3>>>(x, w_k, k, NROWS, DIM, DIM);
    gemm_mma3<<<gg, 256, SMEM_G3>>>(x, w_v, v, NROWS, DIM, DIM);

    sigma_raw_kernel<<<NROWS, 256>>>(q, mnorms, sig, raw);
    rel_kernel<<<NMEM * BATCH, 256>>>(raw, rel);
    cscale_kernel<<<NROWS / 256, 256>>>(raw, rel, csc);

    gemm_mma_mem<<<gg, 256, SMEM_GM>>>(sig, bt, csc, memo);

    flash_attn<<<dim3(SEQ / 64, BATCH * NHEADS), 256, FLASH_SMEM>>>(q, k, v, loc);

    blend_kernel<<<NROWS * DIM / 4 / 256, 256>>>(memo, loc, gate, sig);

    gemm_mma3<<<gg, 256, SMEM_G3>>>(sig, w_o, out, NROWS, DIM, DIM);
}

// round 4
// speedup vs baseline: 1.3720x; 1.1616x over previous
#include <cuda_runtime.h>
#include <cstdint>

#define SEQ    2048
#define BATCH  2
#define NROWS  4096
#define DIM    2048
#define NMEM   4
#define HDIM   128
#define NHEADS 16
#define KTOT   (NMEM*DIM)

// ---------------- scratch ----------------
__device__ float g_q  [NROWS*DIM];
__device__ float g_k  [NROWS*DIM];
__device__ float g_v  [NROWS*DIM];
__device__ float g_sig[NROWS*DIM];   // sigma; later reused as blend buffer
__device__ float g_mem[NROWS*DIM];
__device__ float g_loc[NROWS*DIM];
__device__ float g_bt [DIM*KTOT];    // transposed memories [E=2048][K=8192]
__device__ float g_raw[NMEM*NROWS];
__device__ float g_rel[NMEM*BATCH];
__device__ float g_csc[NMEM*NROWS];

// ---------------- helpers ----------------
#define MMA_TF32(c, a0, a1, a2, a3, b0, b1) \
    asm volatile("mma.sync.aligned.m16n8k8.row.col.f32.tf32.tf32.f32 " \
        "{%0,%1,%2,%3}, {%4,%5,%6,%7}, {%8,%9}, {%0,%1,%2,%3};" \
        : "+f"((c)[0]), "+f"((c)[1]), "+f"((c)[2]), "+f"((c)[3]) \
        : "r"(a0), "r"(a1), "r"(a2), "r"(a3), "r"(b0), "r"(b1))

__device__ __forceinline__ uint32_t f2b(float x) { return __float_as_uint(x); }
__device__ __forceinline__ float tf32_hi(float x) {
    return __uint_as_float(__float_as_uint(x) & 0xFFFFE000u);
}
__device__ __forceinline__ uint32_t smem_u32(const void* p) {
    uint32_t a;
    asm("{ .reg .u64 t; cvta.to.shared.u64 t, %1; cvt.u32.u64 %0, t; }" : "=r"(a) : "l"(p));
    return a;
}
__device__ __forceinline__ void cpasync16(uint32_t dst, const float* src) {
    asm volatile("cp.async.cg.shared.global [%0], [%1], 16;" :: "r"(dst), "l"(src));
}
#define CP_COMMIT() asm volatile("cp.async.commit_group;" ::: "memory")
#define CP_WAIT(n)  asm volatile("cp.async.wait_group %0;" :: "n"(n) : "memory")

// stage layout (floats): A [128][36] then B [128][36] (both fp32, B n-major)
#define STGF   (128*36*2)            // 9216 floats per stage
#define SMEM_G (2*STGF*4)            // 73,728 bytes

// =====================================================================
// 3xTF32 split GEMM, cp.async pipelined: C[M,N] = A[M,K]*B[N,K]^T
// =====================================================================
__global__ void __launch_bounds__(256) gemm_mma3(
    const float* __restrict__ A, const float* __restrict__ B,
    float* __restrict__ C, int M, int N, int K)
{
    extern __shared__ float sm[];
    const int tid = threadIdx.x, lane = tid & 31, wid = tid >> 5;
    const int wm = wid & 3, wn = wid >> 2;
    const int m0 = wm * 32, n0 = wn * 64;
    const int row = lane >> 2, col = lane & 3;
    const int rowBase = blockIdx.y << 7, colBase = blockIdx.x << 7;
    const int lm = tid & 127, lkq = tid >> 7;
    const uint32_t sb = smem_u32(sm);
    const uint32_t ldoff = (uint32_t)(lm * 36 + (lkq << 4)) * 4;

    float c[2][8][4];
    #pragma unroll
    for (int i = 0; i < 2; i++)
        #pragma unroll
        for (int j = 0; j < 8; j++)
            #pragma unroll
            for (int t = 0; t < 4; t++) c[i][j][t] = 0.f;

    const int nt = K >> 5;
    {   // prologue: stage 0 <- tile 0
        const float* Ag = A + (size_t)(rowBase + lm) * K + (lkq << 4);
        const float* Bg = B + (size_t)(colBase + lm) * K + (lkq << 4);
        uint32_t da = sb + ldoff, db = da + 18432;
        #pragma unroll
        for (int u = 0; u < 4; u++) { cpasync16(da + u*16, Ag + u*4); cpasync16(db + u*16, Bg + u*4); }
        CP_COMMIT();
    }
    for (int kt = 0; kt < nt; kt++) {
        const int s = kt & 1;
        if (kt + 1 < nt) {
            const float* Ag = A + (size_t)(rowBase + lm) * K + ((kt + 1) << 5) + (lkq << 4);
            const float* Bg = B + (size_t)(colBase + lm) * K + ((kt + 1) << 5) + (lkq << 4);
            uint32_t da = sb + (uint32_t)(s ^ 1) * (STGF * 4) + ldoff, db = da + 18432;
            #pragma unroll
            for (int u = 0; u < 4; u++) { cpasync16(da + u*16, Ag + u*4); cpasync16(db + u*16, Bg + u*4); }
            CP_COMMIT();
            CP_WAIT(1);
        } else CP_WAIT(0);
        __syncthreads();

        const float* As = sm + s * STGF;
        const float* Bs = As + 4608;
        #pragma unroll
        for (int k8 = 0; k8 < 4; k8++) {
            const int kb = k8 << 3;
            uint32_t ah[2][4], al[2][4];
            #pragma unroll
            for (int i = 0; i < 2; i++) {
                const int mr = m0 + 16 * i + row;
                float a0 = As[mr*36 + kb + col],     a1 = As[(mr+8)*36 + kb + col];
                float a2 = As[mr*36 + kb + col + 4], a3 = As[(mr+8)*36 + kb + col + 4];
                float h0 = tf32_hi(a0), h1 = tf32_hi(a1), h2 = tf32_hi(a2), h3 = tf32_hi(a3);
                ah[i][0]=f2b(h0); ah[i][1]=f2b(h1); ah[i][2]=f2b(h2); ah[i][3]=f2b(h3);
                al[i][0]=f2b(a0-h0); al[i][1]=f2b(a1-h1); al[i][2]=f2b(a2-h2); al[i][3]=f2b(a3-h3);
            }
            #pragma unroll
            for (int j = 0; j < 8; j++) {
                const int nn = n0 + 8 * j + row;
                float b0 = Bs[nn*36 + kb + col], b1 = Bs[nn*36 + kb + col + 4];
                float h0 = tf32_hi(b0), h1 = tf32_hi(b1);
                uint32_t bh0 = f2b(h0), bh1 = f2b(h1);
                uint32_t bl0 = f2b(b0 - h0), bl1 = f2b(b1 - h1);
                #pragma unroll
                for (int i = 0; i < 2; i++) {
                    MMA_TF32(c[i][j], ah[i][0], ah[i][1], ah[i][2], ah[i][3], bh0, bh1);
                    MMA_TF32(c[i][j], al[i][0], al[i][1], al[i][2], al[i][3], bh0, bh1);
                    MMA_TF32(c[i][j], ah[i][0], ah[i][1], ah[i][2], ah[i][3], bl0, bl1);
                }
            }
        }
        __syncthreads();
    }

    #pragma unroll
    for (int i = 0; i < 2; i++) {
        int r0 = rowBase + m0 + i * 16 + row;
        #pragma unroll
        for (int j = 0; j < 8; j++) {
            int cc = colBase + n0 + j * 8 + 2 * col;
            *(float2*)(C + (size_t)r0 * N + cc)       = make_float2(c[i][j][0], c[i][j][1]);
            *(float2*)(C + (size_t)(r0 + 8) * N + cc) = make_float2(c[i][j][2], c[i][j][3]);
        }
    }
}

// =====================================================================
// Single-pass tf32 memory-retrieval GEMM, cp.async pipelined.
// C[4096,2048] = A_ext @ bt^T ; A_ext[r,k] = csc[k>>11, r]*sigma[r, k&2047]
// =====================================================================
__global__ void __launch_bounds__(256) gemm_mma_mem(
    const float* __restrict__ sig, const float* __restrict__ bt,
    const float* __restrict__ csc, float* __restrict__ C)
{
    extern __shared__ float sm[];
    const int tid = threadIdx.x, lane = tid & 31, wid = tid >> 5;
    const int wm = wid & 3, wn = wid >> 2;
    const int m0 = wm * 32, n0 = wn * 64;
    const int row = lane >> 2, col = lane & 3;
    const int rowBase = blockIdx.y << 7, colBase = blockIdx.x << 7;
    const int lm = tid & 127, lkq = tid >> 7;
    const uint32_t sb = smem_u32(sm);
    const uint32_t ldoff = (uint32_t)(lm * 36 + (lkq << 4)) * 4;

    // preload csc for this warp's 4 fragment rows x 4 memories
    float sc[NMEM][4];
    #pragma unroll
    for (int m = 0; m < NMEM; m++) {
        sc[m][0] = csc[m * NROWS + rowBase + m0 + row];
        sc[m][1] = csc[m * NROWS + rowBase + m0 + row + 8];
        sc[m][2] = csc[m * NROWS + rowBase + m0 + row + 16];
        sc[m][3] = csc[m * NROWS + rowBase + m0 + row + 24];
    }

    float c[2][8][4];
    #pragma unroll
    for (int i = 0; i < 2; i++)
        #pragma unroll
        for (int j = 0; j < 8; j++)
            #pragma unroll
            for (int t = 0; t < 4; t++) c[i][j][t] = 0.f;

    const int nt = KTOT >> 5;
    {
        const float* Ag = sig + (size_t)(rowBase + lm) * DIM + (lkq << 4);
        const float* Bg = bt + (size_t)(colBase + lm) * KTOT + (lkq << 4);
        uint32_t da = sb + ldoff, db = da + 18432;
        #pragma unroll
        for (int u = 0; u < 4; u++) { cpasync16(da + u*16, Ag + u*4); cpasync16(db + u*16, Bg + u*4); }
        CP_COMMIT();
    }
    for (int kt = 0; kt < nt; kt++) {
        const int s = kt & 1;
        if (kt + 1 < nt) {
            const int kg = (kt + 1) << 5;
            const float* Ag = sig + (size_t)(rowBase + lm) * DIM + (kg & 2047) + (lkq << 4);
            const float* Bg = bt + (size_t)(colBase + lm) * KTOT + kg + (lkq << 4);
            uint32_t da = sb + (uint32_t)(s ^ 1) * (STGF * 4) + ldoff, db = da + 18432;
            #pragma unroll
            for (int u = 0; u < 4; u++) { cpasync16(da + u*16, Ag + u*4); cpasync16(db + u*16, Bg + u*4); }
            CP_COMMIT();
            CP_WAIT(1);
        } else CP_WAIT(0);
        __syncthreads();

        const int mi = kt >> 6;
        const float* As = sm + s * STGF;
        const float* Bs = As + 4608;
        #pragma unroll
        for (int k8 = 0; k8 < 4; k8++) {
            const int kb = k8 << 3;
            uint32_t a[2][4];
            #pragma unroll
            for (int i = 0; i < 2; i++) {
                const int mr = m0 + 16 * i + row;
                const float s0 = sc[mi][2*i], s1 = sc[mi][2*i+1];
                a[i][0] = f2b(As[mr*36 + kb + col] * s0);
                a[i][1] = f2b(As[(mr+8)*36 + kb + col] * s1);
                a[i][2] = f2b(As[mr*36 + kb + col + 4] * s0);
                a[i][3] = f2b(As[(mr+8)*36 + kb + col + 4] * s1);
            }
            #pragma unroll
            for (int j = 0; j < 8; j++) {
                const int nn = n0 + 8 * j + row;
                uint32_t b0 = f2b(Bs[nn*36 + kb + col]);
                uint32_t b1 = f2b(Bs[nn*36 + kb + col + 4]);
                #pragma unroll
                for (int i = 0; i < 2; i++)
                    MMA_TF32(c[i][j], a[i][0], a[i][1], a[i][2], a[i][3], b0, b1);
            }
        }
        __syncthreads();
    }

    #pragma unroll
    for (int i = 0; i < 2; i++) {
        int r0 = rowBase + m0 + i * 16 + row;
        #pragma unroll
        for (int j = 0; j < 8; j++) {
            int cc = colBase + n0 + j * 8 + 2 * col;
            *(float2*)(C + (size_t)r0 * DIM + cc)       = make_float2(c[i][j][0], c[i][j][1]);
            *(float2*)(C + (size_t)(r0 + 8) * DIM + cc) = make_float2(c[i][j][2], c[i][j][3]);
        }
    }
}

// =====================================================================
// Flash attention (causal) with tf32 mma.sync, 3-pass split on QK and PV.
// 128 q-rows x 64 k-cols per tile; 8 warps x 16 rows.
// =====================================================================
#define QSF 0
#define KSF (128*132)
#define VSF (KSF + 64*132)
#define PSF (VSF + 64*132)
#define FLASH_SMEM ((128*132 + 64*132 + 64*132 + 128*68) * 4)

__global__ void __launch_bounds__(256) flash_mma(
    const float* __restrict__ Q, const float* __restrict__ K,
    const float* __restrict__ V, float* __restrict__ O)
{
    extern __shared__ float sm[];
    float* Qs = sm + QSF;
    float* Ks = sm + KSF;
    float* Vs = sm + VSF;
    float* Ps = sm + PSF;
    const int tid = threadIdx.x, lane = tid & 31, wid = tid >> 5;
    const int row = lane >> 2, col = lane & 3;
    const int r0 = wid * 16;
    const int qb = blockIdx.x;               // 0..15 (128 rows each)
    const int bh = blockIdx.y;
    const int b = bh >> 4, h = bh & 15;
    const float scale = 0.08838834764831845f;

    // load Q tile [128][128]
    const float* Qg = Q + (size_t)(b * SEQ + qb * 128) * DIM + h * HDIM;
    #pragma unroll
    for (int t = 0; t < 16; t++) {
        int f = tid + t * 256;
        int r = f >> 5, c = (f & 31) << 2;
        *(float4*)&Qs[r * 132 + c] = *(const float4*)(Qg + (size_t)r * DIM + c);
    }

    float o[16][4];
    #pragma unroll
    for (int nf = 0; nf < 16; nf++)
        #pragma unroll
        for (int t = 0; t < 4; t++) o[nf][t] = 0.f;
    float m0v = -1e30f, m1v = -1e30f, l0 = 0.f, l1 = 0.f;

    const int ktmax = 2 * qb + 1;
    const int rg0 = qb * 128 + r0 + row;
    const int rg1 = rg0 + 8;

    for (int kt = 0; kt <= ktmax; kt++) {
        const float* Kg = K + (size_t)(b * SEQ + kt * 64) * DIM + h * HDIM;
        const float* Vg = V + (size_t)(b * SEQ + kt * 64) * DIM + h * HDIM;
        __syncthreads();     // previous iteration done with Ks/Vs
        #pragma unroll
        for (int t = 0; t < 8; t++) {
            int f = tid + t * 256;
            int r = f >> 5, c = (f & 31) << 2;
            *(float4*)&Ks[r * 132 + c] = *(const float4*)(Kg + (size_t)r * DIM + c);
            *(float4*)&Vs[r * 132 + c] = *(const float4*)(Vg + (size_t)r * DIM + c);
        }
        __syncthreads();

        // ---- S = Q K^T (3-pass tf32 split), S tile 16x64 per warp ----
        float sf[8][4];
        #pragma unroll
        for (int j = 0; j < 8; j++)
            #pragma unroll
            for (int t = 0; t < 4; t++) sf[j][t] = 0.f;

        #pragma unroll
        for (int k8 = 0; k8 < 16; k8++) {
            const int kb = k8 << 3;
            float q0 = Qs[(r0+row)*132 + kb + col],     q1 = Qs[(r0+row+8)*132 + kb + col];
            float q2 = Qs[(r0+row)*132 + kb + col + 4], q3 = Qs[(r0+row+8)*132 + kb + col + 4];
            float qh0 = tf32_hi(q0), qh1 = tf32_hi(q1), qh2 = tf32_hi(q2), qh3 = tf32_hi(q3);
            uint32_t ah0 = f2b(qh0), ah1 = f2b(qh1), ah2 = f2b(qh2), ah3 = f2b(qh3);
            uint32_t al0 = f2b(q0-qh0), al1 = f2b(q1-qh1), al2 = f2b(q2-qh2), al3 = f2b(q3-qh3);
            #pragma unroll
            for (int j = 0; j < 8; j++) {
                float b0 = Ks[(8*j+row)*132 + kb + col], b1 = Ks[(8*j+row)*132 + kb + col + 4];
                float h0 = tf32_hi(b0), h1 = tf32_hi(b1);
                uint32_t bh0 = f2b(h0), bh1 = f2b(h1);
                uint32_t bl0 = f2b(b0-h0), bl1 = f2b(b1-h1);
                MMA_TF32(sf[j], ah0, ah1, ah2, ah3, bh0, bh1);
                MMA_TF32(sf[j], al0, al1, al2, al3, bh0, bh1);
                MMA_TF32(sf[j], ah0, ah1, ah2, ah3, bl0, bl1);
            }
        }

        // scale + causal mask
        #pragma unroll
        for (int j = 0; j < 8; j++)
            #pragma unroll
            for (int t = 0; t < 4; t++) sf[j][t] *= scale;
        if (kt >= 2 * qb) {
            #pragma unroll
            for (int j = 0; j < 8; j++) {
                int cg = (kt << 6) + 8 * j + 2 * col;
                if (cg     > rg0) sf[j][0] = -1e30f;
                if (cg + 1 > rg0) sf[j][1] = -1e30f;
                if (cg     > rg1) sf[j][2] = -1e30f;
                if (cg + 1 > rg1) sf[j][3] = -1e30f;
            }
        }

        // online softmax (rows rg0, rg1 per lane; quad = lanes sharing row)
        float mx0 = -1e30f, mx1 = -1e30f;
        #pragma unroll
        for (int j = 0; j < 8; j++) {
            mx0 = fmaxf(mx0, fmaxf(sf[j][0], sf[j][1]));
            mx1 = fmaxf(mx1, fmaxf(sf[j][2], sf[j][3]));
        }
        mx0 = fmaxf(mx0, __shfl_xor_sync(0xffffffffu, mx0, 1));
        mx0 = fmaxf(mx0, __shfl_xor_sync(0xffffffffu, mx0, 2));
        mx1 = fmaxf(mx1, __shfl_xor_sync(0xffffffffu, mx1, 1));
        mx1 = fmaxf(mx1, __shfl_xor_sync(0xffffffffu, mx1, 2));
        float mn0 = fmaxf(m0v, mx0), mn1 = fmaxf(m1v, mx1);
        float corr0 = __expf(m0v - mn0), corr1 = __expf(m1v - mn1);
        float rs0 = 0.f, rs1 = 0.f;
        #pragma unroll
        for (int j = 0; j < 8; j++) {
            float p0 = __expf(sf[j][0] - mn0);
            float p1 = __expf(sf[j][1] - mn0);
            float p2 = __expf(sf[j][2] - mn1);
            float p3 = __expf(sf[j][3] - mn1);
            Ps[(r0+row)*68 + 8*j + 2*col]       = p0;
            Ps[(r0+row)*68 + 8*j + 2*col + 1]   = p1;
            Ps[(r0+row+8)*68 + 8*j + 2*col]     = p2;
            Ps[(r0+row+8)*68 + 8*j + 2*col + 1] = p3;
            rs0 += p0 + p1; rs1 += p2 + p3;
        }
        rs0 += __shfl_xor_sync(0xffffffffu, rs0, 1);
        rs0 += __shfl_xor_sync(0xffffffffu, rs0, 2);
        rs1 += __shfl_xor_sync(0xffffffffu, rs1, 1);
        rs1 += __shfl_xor_sync(0xffffffffu, rs1, 2);
        l0 = l0 * corr0 + rs0;  l1 = l1 * corr1 + rs1;
        m0v = mn0; m1v = mn1;
        #pragma unroll
        for (int nf = 0; nf < 16; nf++) {
            o[nf][0] *= corr0; o[nf][1] *= corr0;
            o[nf][2] *= corr1; o[nf][3] *= corr1;
        }
        __syncwarp();   // P visible within warp (P rows are warp-private)

        // ---- O += P V (3-pass tf32 split) ----
        #pragma unroll
        for (int k8 = 0; k8 < 8; k8++) {
            const int kb = k8 << 3;
            float p0 = Ps[(r0+row)*68 + kb + col],     p1 = Ps[(r0+row+8)*68 + kb + col];
            float p2 = Ps[(r0+row)*68 + kb + col + 4], p3 = Ps[(r0+row+8)*68 + kb + col + 4];
            float ph0 = tf32_hi(p0), ph1 = tf32_hi(p1), ph2 = tf32_hi(p2), ph3 = tf32_hi(p3);
            uint32_t ah0 = f2b(ph0), ah1 = f2b(ph1), ah2 = f2b(ph2), ah3 = f2b(ph3);
            uint32_t al0 = f2b(p0-ph0), al1 = f2b(p1-ph1), al2 = f2b(p2-ph2), al3 = f2b(p3-ph3);
            #pragma unroll
            for (int nf = 0; nf < 16; nf++) {
                float v0 = Vs[(kb+col)*132 + 8*nf + row], v1 = Vs[(kb+col+4)*132 + 8*nf + row];
                float h0 = tf32_hi(v0), h1 = tf32_hi(v1);
                uint32_t bh0 = f2b(h0), bh1 = f2b(h1);
                uint32_t bl0 = f2b(v0-h0), bl1 = f2b(v1-h1);
                MMA_TF32(o[nf], ah0, ah1, ah2, ah3, bh0, bh1);
                MMA_TF32(o[nf], al0, al1, al2, al3, bh0, bh1);
                MMA_TF32(o[nf], ah0, ah1, ah2, ah3, bl0, bl1);
            }
        }
    }

    const float inv0 = 1.f / l0, inv1 = 1.f / l1;
    float* Op0 = O + (size_t)(b * SEQ + qb * 128 + r0 + row) * DIM + h * HDIM;
    float* Op1 = Op0 + 8 * DIM;
    #pragma unroll
    for (int nf = 0; nf < 16; nf++) {
        int cc = 8 * nf + 2 * col;
        *(float2*)(Op0 + cc) = make_float2(o[nf][0] * inv0, o[nf][1] * inv0);
        *(float2*)(Op1 + cc) = make_float2(o[nf][2] * inv1, o[nf][3] * inv1);
    }
}

// =====================================================================
// memories [M,D,E] -> bt [E][m*D+d]
// =====================================================================
__global__ void transpose_mem(const float* __restrict__ mem, float* __restrict__ bt)
{
    __shared__ float t[32][33];
    const int m = blockIdx.z;
    const int d0 = blockIdx.x << 5, e0 = blockIdx.y << 5;
    const float* src = mem + ((size_t)m * DIM + d0) * DIM + e0;
    for (int i = threadIdx.y; i < 32; i += 8)
        t[i][threadIdx.x] = src[(size_t)i * DIM + threadIdx.x];
    __syncthreads();
    float* dst = bt + (size_t)e0 * KTOT + m * DIM + d0;
    for (int i = threadIdx.y; i < 32; i += 8)
        dst[(size_t)i * KTOT + threadIdx.x] = t[threadIdx.x][i];
}

// =====================================================================
// sigma / raw / rel / cscale / blend
// =====================================================================
__inline__ __device__ float warpReduceSum(float v) {
    #pragma unroll
    for (int o = 16; o > 0; o >>= 1) v += __shfl_down_sync(0xffffffffu, v, o);
    return v;
}

__global__ void __launch_bounds__(256) sigma_raw_kernel(
    const float* __restrict__ q, const float* __restrict__ norms,
    float* __restrict__ sig, float* __restrict__ raw)
{
    const int r = blockIdx.x;
    const int base = r * DIM;
    float a[NMEM] = {0.f, 0.f, 0.f, 0.f};
    for (int c = threadIdx.x * 4; c < DIM; c += 1024) {
        float4 qv = *(const float4*)(q + base + c);
        float4 s;
        s.x = qv.x > 0.f ? qv.x + 1.f : __expf(qv.x);
        s.y = qv.y > 0.f ? qv.y + 1.f : __expf(qv.y);
        s.z = qv.z > 0.f ? qv.z + 1.f : __expf(qv.z);
        s.w = qv.w > 0.f ? qv.w + 1.f : __expf(qv.w);
        *(float4*)(sig + base + c) = s;
        #pragma unroll
        for (int m = 0; m < NMEM; m++) {
            float4 nv = *(const float4*)(norms + m * DIM + c);
            a[m] += s.x * nv.x + s.y * nv.y + s.z * nv.z + s.w * nv.w;
        }
    }
    __shared__ float red[NMEM][8];
    const int lane = threadIdx.x & 31, wid = threadIdx.x >> 5;
    #pragma unroll
    for (int m = 0; m < NMEM; m++) a[m] = warpReduceSum(a[m]);
    if (lane == 0)
        #pragma unroll
        for (int m = 0; m < NMEM; m++) red[m][wid] = a[m];
    __syncthreads();
    if (wid == 0) {
        #pragma unroll
        for (int m = 0; m < NMEM; m++) {
            float v = (lane < 8) ? red[m][lane] : 0.f;
            v = warpReduceSum(v);
            if (lane == 0) raw[m * NROWS + r] = v;
        }
    }
}

__global__ void __launch_bounds__(256) rel_kernel(
    const float* __restrict__ raw, float* __restrict__ rel)
{
    const int m = blockIdx.x >> 1, b = blockIdx.x & 1;
    float acc = 0.f;
    for (int s = threadIdx.x; s < SEQ; s += 256) acc += raw[m * NROWS + b * SEQ + s];
    __shared__ float red[8];
    const int lane = threadIdx.x & 31, wid = threadIdx.x >> 5;
    acc = warpReduceSum(acc);
    if (lane == 0) red[wid] = acc;
    __syncthreads();
    if (threadIdx.x == 0) {
        float t = 0.f;
        #pragma unroll
        for (int w = 0; w < 8; w++) t += red[w];
        rel[m * BATCH + b] = t / (float)SEQ;
    }
}

__global__ void __launch_bounds__(256) cscale_kernel(
    const float* __restrict__ raw, const float* __restrict__ rel,
    float* __restrict__ csc)
{
    const int r = blockIdx.x * 256 + threadIdx.x;
    if (r >= NROWS) return;
    const int b = r >> 11;
    float e[NMEM];
    #pragma unroll
    for (int m = 0; m < NMEM; m++) e[m] = rel[m * BATCH + b];
    float mx = fmaxf(fmaxf(e[0], e[1]), fmaxf(e[2], e[3]));
    float w[NMEM], sum = 0.f;
    #pragma unroll
    for (int m = 0; m < NMEM; m++) { w[m] = __expf(e[m] - mx); sum += w[m]; }
    const float inv = 1.f / sum;
    #pragma unroll
    for (int m = 0; m < NMEM; m++)
        csc[m * NROWS + r] = w[m] * inv / fmaxf(raw[m * NROWS + r], 1e-6f);
}

__global__ void __launch_bounds__(256) blend_kernel(
    const float* __restrict__ mem, const float* __restrict__ loc,
    const float* __restrict__ gate, float* __restrict__ bl)
{
    const int i = blockIdx.x * 256 + threadIdx.x;
    const float g = 1.f / (1.f + __expf(-gate[0]));
    const float gi = 1.f - g;
    float4 m = ((const float4*)mem)[i], l = ((const float4*)loc)[i];
    ((float4*)bl)[i] = make_float4(g*m.x + gi*l.x, g*m.y + gi*l.y,
                                   g*m.z + gi*l.z, g*m.w + gi*l.w);
}

// =====================================================================
extern "C" void kernel_launch(void* const* d_in, const int* in_sizes, int n_in,
                              void* d_out, int out_size)
{
    const float* x        = (const float*)d_in[0];
    const float* w_q      = (const float*)d_in[1];
    const float* w_k      = (const float*)d_in[2];
    const float* w_v      = (const float*)d_in[3];
    const float* w_o      = (const float*)d_in[4];
    const float* gate     = (const float*)d_in[5];
    const float* memories = (const float*)d_in[6];
    const float* mnorms   = (const float*)d_in[7];
    float* out = (float*)d_out;

    float *q, *k, *v, *sig, *memo, *loc, *bt, *raw, *rel, *csc;
    cudaGetSymbolAddress((void**)&q,    g_q);
    cudaGetSymbolAddress((void**)&k,    g_k);
    cudaGetSymbolAddress((void**)&v,    g_v);
    cudaGetSymbolAddress((void**)&sig,  g_sig);
    cudaGetSymbolAddress((void**)&memo, g_mem);
    cudaGetSymbolAddress((void**)&loc,  g_loc);
    cudaGetSymbolAddress((void**)&bt,   g_bt);
    cudaGetSymbolAddress((void**)&raw,  g_raw);
    cudaGetSymbolAddress((void**)&rel,  g_rel);
    cudaGetSymbolAddress((void**)&csc,  g_csc);

    cudaFuncSetAttribute(gemm_mma3,    cudaFuncAttributeMaxDynamicSharedMemorySize, SMEM_G);
    cudaFuncSetAttribute(gemm_mma_mem, cudaFuncAttributeMaxDynamicSharedMemorySize, SMEM_G);
    cudaFuncSetAttribute(flash_mma,    cudaFuncAttributeMaxDynamicSharedMemorySize, FLASH_SMEM);

    dim3 gg(DIM / 128, NROWS / 128);   // (16, 32)

    transpose_mem<<<dim3(DIM / 32, DIM / 32, NMEM), dim3(32, 8)>>>(memories, bt);

    gemm_mma3<<<gg, 256, SMEM_G>>>(x, w_q, q, NROWS, DIM, DIM);
    gemm_mma3<<<gg, 256, SMEM_G>>>(x, w_k, k, NROWS, DIM, DIM);
    gemm_mma3<<<gg, 256, SMEM_G>>>(x, w_v, v, NROWS, DIM, DIM);

    sigma_raw_kernel<<<NROWS, 256>>>(q, mnorms, sig, raw);
    rel_kernel<<<NMEM * BATCH, 256>>>(raw, rel);
    cscale_kernel<<<NROWS / 256, 256>>>(raw, rel, csc);

    gemm_mma_mem<<<gg, 256, SMEM_G>>>(sig, bt, csc, memo);

    flash_mma<<<dim3(SEQ / 128, BATCH * NHEADS), 256, FLASH_SMEM>>>(q, k, v, loc);

    blend_kernel<<<NROWS * DIM / 4 / 256, 256>>>(memo, loc, gate, sig);

    gemm_mma3<<<gg, 256, SMEM_G>>>(sig, w_o, out, NROWS, DIM, DIM);
}

// round 5
// speedup vs baseline: 1.9156x; 1.3962x over previous
#include <cuda_runtime.h>
#include <cuda_fp16.h>
#include <cuda_bf16.h>
#include <cstdint>

#define SEQ    2048
#define BATCH  2
#define NROWS  4096
#define DIM    2048
#define NMEM   4
#define HDIM   128
#define NHEADS 16
#define KTOT   (NMEM*DIM)

// ---------------- scratch ----------------
__device__ float g_q  [NROWS*DIM];
__device__ float g_k  [NROWS*DIM];
__device__ float g_v  [NROWS*DIM];
__device__ float g_sig[NROWS*DIM];   // sigma fp32; later reused as blend buffer
__device__ float g_mem[NROWS*DIM];
__device__ float g_loc[NROWS*DIM];
__device__ __nv_bfloat16 g_bt[DIM*KTOT];       // transposed memories bf16 [E=2048][K=8192]
__device__ __nv_bfloat16 g_as[NROWS*KTOT];     // csc-scaled sigma bf16 [4096][8192]
__device__ float g_raw[NMEM*NROWS];
__device__ float g_rel[NMEM*BATCH];
__device__ float g_csc[NMEM*NROWS];

// ---------------- mma helpers ----------------
#define MMA_F16(c, a0,a1,a2,a3, b0,b1) \
    asm volatile("mma.sync.aligned.m16n8k16.row.col.f32.f16.f16.f32 " \
        "{%0,%1,%2,%3}, {%4,%5,%6,%7}, {%8,%9}, {%0,%1,%2,%3};" \
        : "+f"((c)[0]), "+f"((c)[1]), "+f"((c)[2]), "+f"((c)[3]) \
        : "r"(a0), "r"(a1), "r"(a2), "r"(a3), "r"(b0), "r"(b1))

#define MMA_BF16(c, a0,a1,a2,a3, b0,b1) \
    asm volatile("mma.sync.aligned.m16n8k16.row.col.f32.bf16.bf16.f32 " \
        "{%0,%1,%2,%3}, {%4,%5,%6,%7}, {%8,%9}, {%0,%1,%2,%3};" \
        : "+f"((c)[0]), "+f"((c)[1]), "+f"((c)[2]), "+f"((c)[3]) \
        : "r"(a0), "r"(a1), "r"(a2), "r"(a3), "r"(b0), "r"(b1))

#define MMA_TF32(c, a0, a1, a2, a3, b0, b1) \
    asm volatile("mma.sync.aligned.m16n8k8.row.col.f32.tf32.tf32.f32 " \
        "{%0,%1,%2,%3}, {%4,%5,%6,%7}, {%8,%9}, {%0,%1,%2,%3};" \
        : "+f"((c)[0]), "+f"((c)[1]), "+f"((c)[2]), "+f"((c)[3]) \
        : "r"(a0), "r"(a1), "r"(a2), "r"(a3), "r"(b0), "r"(b1))

__device__ __forceinline__ uint32_t f2b(float x) { return __float_as_uint(x); }
__device__ __forceinline__ float tf32_hi(float x) {
    return __uint_as_float(__float_as_uint(x) & 0xFFFFE000u);
}
__device__ __forceinline__ uint32_t smem_u32(const void* p) {
    uint32_t a;
    asm("{ .reg .u64 t; cvta.to.shared.u64 t, %1; cvt.u32.u64 %0, t; }" : "=r"(a) : "l"(p));
    return a;
}
__device__ __forceinline__ void cpasync16(uint32_t dst, const void* src) {
    asm volatile("cp.async.cg.shared.global [%0], [%1], 16;" :: "r"(dst), "l"(src));
}
#define CP_COMMIT() asm volatile("cp.async.commit_group;" ::: "memory")
#define CP_WAIT(n)  asm volatile("cp.async.wait_group %0;" :: "n"(n) : "memory")

__device__ __forceinline__ uint32_t ldh2(const __half* p, int hoff) {
    return *(const uint32_t*)(p + hoff);
}
__device__ __forceinline__ uint32_t ldb2(const __nv_bfloat16* p, int off) {
    return *(const uint32_t*)(p + off);
}

// split fp32 quad into fp16 hi/lo planes, store 4 halves per plane (8B each)
__device__ __forceinline__ void store_h2pair(__half* P1, __half* P2, int hoff, float4 v) {
    __half2 h01 = __floats2half2_rn(v.x, v.y);
    __half2 h23 = __floats2half2_rn(v.z, v.w);
    float2 f01 = __half22float2(h01);
    float2 f23 = __half22float2(h23);
    __half2 l01 = __floats2half2_rn(v.x - f01.x, v.y - f01.y);
    __half2 l23 = __floats2half2_rn(v.z - f23.x, v.w - f23.y);
    *(uint2*)(P1 + hoff) = make_uint2(*(uint32_t*)&h01, *(uint32_t*)&h23);
    *(uint2*)(P2 + hoff) = make_uint2(*(uint32_t*)&l01, *(uint32_t*)&l23);
}

// =====================================================================
// fp16x2 3-pass GEMM (fp32-accurate): C[M,N] = A[M,K] * B[N,K]^T
// 128x128 tile, BK=32, 512 threads (16 warps 4x4), warp tile 32x32.
// Register-prefetch double buffer; smem = fp16 planes A1,A2,B1,B2 [128][36]h.
// blockIdx.z selects (B, C) pair for fused QKV.
// =====================================================================
#define H2PLANE (128*36)
#define H2STAGE (4*H2PLANE)            // halves per stage
#define SMEM_H2 (2*H2STAGE*2)          // bytes

__global__ void __launch_bounds__(512) gemm_h2(
    const float* __restrict__ A,
    const float* __restrict__ B0, const float* __restrict__ B1p, const float* __restrict__ B2p,
    float* __restrict__ C0, float* __restrict__ C1p, float* __restrict__ C2p,
    int M, int N, int K)
{
    extern __shared__ __half smh[];
    const float* B = (blockIdx.z == 0) ? B0 : (blockIdx.z == 1) ? B1p : B2p;
    float* C       = (blockIdx.z == 0) ? C0 : (blockIdx.z == 1) ? C1p : C2p;

    const int tid = threadIdx.x, lane = tid & 31, wid = tid >> 5;
    const int m0 = (wid & 3) * 32, n0 = (wid >> 2) * 32;
    const int row = lane >> 2, col = lane & 3;
    const int rowBase = blockIdx.y << 7, colBase = blockIdx.x << 7;
    const int lm = tid & 127, kq = tid >> 7;       // loader row, k-octet 0..3

    float c[2][4][4];
    #pragma unroll
    for (int i = 0; i < 2; i++)
        #pragma unroll
        for (int j = 0; j < 4; j++)
            #pragma unroll
            for (int t = 0; t < 4; t++) c[i][j][t] = 0.f;

    const int nt = K >> 5;
    float4 a4[2], b4[2];
    {   // prologue
        const float* Ag = A + (size_t)(rowBase + lm) * K + kq * 8;
        const float* Bg = B + (size_t)(colBase + lm) * K + kq * 8;
        a4[0] = *(const float4*)Ag;     a4[1] = *(const float4*)(Ag + 4);
        b4[0] = *(const float4*)Bg;     b4[1] = *(const float4*)(Bg + 4);
        __half* dA1 = smh;
        const int hoff = lm * 36 + kq * 8;
        store_h2pair(dA1,               dA1 + H2PLANE,   hoff,     a4[0]);
        store_h2pair(dA1,               dA1 + H2PLANE,   hoff + 4, a4[1]);
        store_h2pair(dA1 + 2*H2PLANE,   dA1 + 3*H2PLANE, hoff,     b4[0]);
        store_h2pair(dA1 + 2*H2PLANE,   dA1 + 3*H2PLANE, hoff + 4, b4[1]);
    }
    for (int kt = 0; kt < nt; kt++) {
        const int s = kt & 1;
        __syncthreads();
        if (kt + 1 < nt) {
            const float* Ag = A + (size_t)(rowBase + lm) * K + ((kt + 1) << 5) + kq * 8;
            const float* Bg = B + (size_t)(colBase + lm) * K + ((kt + 1) << 5) + kq * 8;
            a4[0] = *(const float4*)Ag;     a4[1] = *(const float4*)(Ag + 4);
            b4[0] = *(const float4*)Bg;     b4[1] = *(const float4*)(Bg + 4);
        }
        const __half* A1 = smh + s * H2STAGE;
        const __half* A2 = A1 + H2PLANE;
        const __half* Bh = A1 + 2*H2PLANE;
        const __half* Bl = A1 + 3*H2PLANE;
        #pragma unroll
        for (int kf = 0; kf < 2; kf++) {
            const int kb = kf << 4;
            uint32_t ah[2][4], al[2][4];
            #pragma unroll
            for (int i = 0; i < 2; i++) {
                const int base = (m0 + 16*i + row) * 36 + kb + 2*col;
                ah[i][0] = ldh2(A1, base);            ah[i][1] = ldh2(A1, base + 8*36);
                ah[i][2] = ldh2(A1, base + 8);        ah[i][3] = ldh2(A1, base + 8*36 + 8);
                al[i][0] = ldh2(A2, base);            al[i][1] = ldh2(A2, base + 8*36);
                al[i][2] = ldh2(A2, base + 8);        al[i][3] = ldh2(A2, base + 8*36 + 8);
            }
            #pragma unroll
            for (int j = 0; j < 4; j++) {
                const int nb = (n0 + 8*j + row) * 36 + kb + 2*col;
                uint32_t bh0 = ldh2(Bh, nb), bh1 = ldh2(Bh, nb + 8);
                uint32_t bl0 = ldh2(Bl, nb), bl1 = ldh2(Bl, nb + 8);
                #pragma unroll
                for (int i = 0; i < 2; i++) {
                    MMA_F16(c[i][j], ah[i][0], ah[i][1], ah[i][2], ah[i][3], bh0, bh1);
                    MMA_F16(c[i][j], al[i][0], al[i][1], al[i][2], al[i][3], bh0, bh1);
                    MMA_F16(c[i][j], ah[i][0], ah[i][1], ah[i][2], ah[i][3], bl0, bl1);
                }
            }
        }
        if (kt + 1 < nt) {
            __half* dA1 = smh + (s ^ 1) * H2STAGE;
            const int hoff = lm * 36 + kq * 8;
            store_h2pair(dA1,               dA1 + H2PLANE,   hoff,     a4[0]);
            store_h2pair(dA1,               dA1 + H2PLANE,   hoff + 4, a4[1]);
            store_h2pair(dA1 + 2*H2PLANE,   dA1 + 3*H2PLANE, hoff,     b4[0]);
            store_h2pair(dA1 + 2*H2PLANE,   dA1 + 3*H2PLANE, hoff + 4, b4[1]);
        }
    }

    #pragma unroll
    for (int i = 0; i < 2; i++) {
        int r0 = rowBase + m0 + 16*i + row;
        #pragma unroll
        for (int j = 0; j < 4; j++) {
            int cc = colBase + n0 + 8*j + 2*col;
            *(float2*)(C + (size_t)r0 * N + cc)       = make_float2(c[i][j][0], c[i][j][1]);
            *(float2*)(C + (size_t)(r0 + 8) * N + cc) = make_float2(c[i][j][2], c[i][j][3]);
        }
    }
}

// =====================================================================
// bf16 single-pass memory-retrieval GEMM, cp.async pipelined.
// C[4096,2048] = g_as[4096,8192] @ g_bt[2048,8192]^T  (both bf16)
// 128x128 tile, BK=32, 512 threads, warp tile 32x32, stride 40 bf16.
// =====================================================================
#define MBSTGB 20480                  // bytes per stage (A 10240 + B 10240)
#define SMEM_MB (2*MBSTGB)

__global__ void __launch_bounds__(512) gemm_mem_bf(
    const __nv_bfloat16* __restrict__ As, const __nv_bfloat16* __restrict__ Bt,
    float* __restrict__ C)
{
    extern __shared__ __nv_bfloat16 smb[];
    const int tid = threadIdx.x, lane = tid & 31, wid = tid >> 5;
    const int m0 = (wid & 3) * 32, n0 = (wid >> 2) * 32;
    const int row = lane >> 2, col = lane & 3;
    const int rowBase = blockIdx.y << 7, colBase = blockIdx.x << 7;
    const int lrow = tid >> 2, seg = tid & 3;
    const uint32_t sb = smem_u32(smb);
    const uint32_t doff = (uint32_t)(lrow * 80 + seg * 16);

    float c[2][4][4];
    #pragma unroll
    for (int i = 0; i < 2; i++)
        #pragma unroll
        for (int j = 0; j < 4; j++)
            #pragma unroll
            for (int t = 0; t < 4; t++) c[i][j][t] = 0.f;

    const int nt = KTOT >> 5;
    {
        cpasync16(sb + doff,         As + (size_t)(rowBase + lrow) * KTOT + seg * 8);
        cpasync16(sb + 10240 + doff, Bt + (size_t)(colBase + lrow) * KTOT + seg * 8);
        CP_COMMIT();
    }
    for (int kt = 0; kt < nt; kt++) {
        const int s = kt & 1;
        if (kt + 1 < nt) {
            const int kg = (kt + 1) << 5;
            uint32_t d = sb + (uint32_t)(s ^ 1) * MBSTGB + doff;
            cpasync16(d,         As + (size_t)(rowBase + lrow) * KTOT + kg + seg * 8);
            cpasync16(d + 10240, Bt + (size_t)(colBase + lrow) * KTOT + kg + seg * 8);
            CP_COMMIT();
            CP_WAIT(1);
        } else CP_WAIT(0);
        __syncthreads();

        const __nv_bfloat16* Ab = smb + s * (MBSTGB/2);
        const __nv_bfloat16* Bb = Ab + 5120;
        #pragma unroll
        for (int kf = 0; kf < 2; kf++) {
            const int kb = kf << 4;
            uint32_t a[2][4];
            #pragma unroll
            for (int i = 0; i < 2; i++) {
                const int base = (m0 + 16*i + row) * 40 + kb + 2*col;
                a[i][0] = ldb2(Ab, base);       a[i][1] = ldb2(Ab, base + 8*40);
                a[i][2] = ldb2(Ab, base + 8);   a[i][3] = ldb2(Ab, base + 8*40 + 8);
            }
            #pragma unroll
            for (int j = 0; j < 4; j++) {
                const int nb = (n0 + 8*j + row) * 40 + kb + 2*col;
                uint32_t b0 = ldb2(Bb, nb), b1 = ldb2(Bb, nb + 8);
                #pragma unroll
                for (int i = 0; i < 2; i++)
                    MMA_BF16(c[i][j], a[i][0], a[i][1], a[i][2], a[i][3], b0, b1);
            }
        }
        __syncthreads();
    }

    #pragma unroll
    for (int i = 0; i < 2; i++) {
        int r0 = rowBase + m0 + 16*i + row;
        #pragma unroll
        for (int j = 0; j < 4; j++) {
            int cc = colBase + n0 + 8*j + 2*col;
            *(float2*)(C + (size_t)r0 * DIM + cc)       = make_float2(c[i][j][0], c[i][j][1]);
            *(float2*)(C + (size_t)(r0 + 8) * DIM + cc) = make_float2(c[i][j][2], c[i][j][3]);
        }
    }
}

// =====================================================================
// Flash attention (causal): QK^T fp16x2 3-pass mma, PV tf32 3-pass mma.
// 128 q-rows x 64 k-cols per tile; 8 warps x 16 rows. 256 threads.
// =====================================================================
#define FQ1 0
#define FQ2 (FQ1 + 128*136)            // halves
#define FK1 (FQ2 + 128*136)
#define FK2 (FK1 + 64*136)
#define FVS ((FK2 + 64*136) * 2)       // byte offset of V (fp32)
#define FPS (FVS + 64*132*4)           // byte offset of P (fp32)
#define FLASH_SMEM (FPS + 128*68*4)

__global__ void __launch_bounds__(256) flash_mma(
    const float* __restrict__ Q, const float* __restrict__ K,
    const float* __restrict__ V, float* __restrict__ O)
{
    extern __shared__ char sms[];
    __half* Q1 = (__half*)sms + FQ1;
    __half* Q2 = (__half*)sms + FQ2;
    __half* K1 = (__half*)sms + FK1;
    __half* K2 = (__half*)sms + FK2;
    float*  Vs = (float*)(sms + FVS);
    float*  Ps = (float*)(sms + FPS);

    const int tid = threadIdx.x, lane = tid & 31, wid = tid >> 5;
    const int row = lane >> 2, col = lane & 3;
    const int r0 = wid * 16;
    const int qb = blockIdx.x;
    const int bh = blockIdx.y;
    const int b = bh >> 4, h = bh & 15;
    const float scale = 0.08838834764831845f;

    // load Q tile [128][128] -> fp16 hi/lo planes
    const float* Qg = Q + (size_t)(b * SEQ + qb * 128) * DIM + h * HDIM;
    #pragma unroll
    for (int t = 0; t < 16; t++) {
        int f = tid + t * 256;
        int r = f >> 5, c = (f & 31) << 2;
        float4 v = *(const float4*)(Qg + (size_t)r * DIM + c);
        store_h2pair(Q1, Q2, r * 136 + c, v);
    }

    float o[16][4];
    #pragma unroll
    for (int nf = 0; nf < 16; nf++)
        #pragma unroll
        for (int t = 0; t < 4; t++) o[nf][t] = 0.f;
    float m0v = -1e30f, m1v = -1e30f, l0 = 0.f, l1 = 0.f;

    const int ktmax = 2 * qb + 1;
    const int rg0 = qb * 128 + r0 + row;
    const int rg1 = rg0 + 8;

    for (int kt = 0; kt <= ktmax; kt++) {
        const float* Kg = K + (size_t)(b * SEQ + kt * 64) * DIM + h * HDIM;
        const float* Vg = V + (size_t)(b * SEQ + kt * 64) * DIM + h * HDIM;
        __syncthreads();
        #pragma unroll
        for (int t = 0; t < 8; t++) {
            int f = tid + t * 256;
            int r = f >> 5, c = (f & 31) << 2;
            float4 kv = *(const float4*)(Kg + (size_t)r * DIM + c);
            store_h2pair(K1, K2, r * 136 + c, kv);
            *(float4*)&Vs[r * 132 + c] = *(const float4*)(Vg + (size_t)r * DIM + c);
        }
        __syncthreads();

        // ---- S = Q K^T : fp16x2 3-pass, warp tile 16x64 ----
        float sf[8][4];
        #pragma unroll
        for (int j = 0; j < 8; j++)
            #pragma unroll
            for (int t = 0; t < 4; t++) sf[j][t] = 0.f;

        #pragma unroll
        for (int kf = 0; kf < 8; kf++) {
            const int kb = kf << 4;
            const int abase = (r0 + row) * 136 + kb + 2*col;
            uint32_t ah0 = ldh2(Q1, abase),          ah1 = ldh2(Q1, abase + 8*136);
            uint32_t ah2 = ldh2(Q1, abase + 8),      ah3 = ldh2(Q1, abase + 8*136 + 8);
            uint32_t al0 = ldh2(Q2, abase),          al1 = ldh2(Q2, abase + 8*136);
            uint32_t al2 = ldh2(Q2, abase + 8),      al3 = ldh2(Q2, abase + 8*136 + 8);
            #pragma unroll
            for (int j = 0; j < 8; j++) {
                const int nb = (8*j + row) * 136 + kb + 2*col;
                uint32_t bh0 = ldh2(K1, nb), bh1 = ldh2(K1, nb + 8);
                uint32_t bl0 = ldh2(K2, nb), bl1 = ldh2(K2, nb + 8);
                MMA_F16(sf[j], ah0, ah1, ah2, ah3, bh0, bh1);
                MMA_F16(sf[j], al0, al1, al2, al3, bh0, bh1);
                MMA_F16(sf[j], ah0, ah1, ah2, ah3, bl0, bl1);
            }
        }

        #pragma unroll
        for (int j = 0; j < 8; j++)
            #pragma unroll
            for (int t = 0; t < 4; t++) sf[j][t] *= scale;
        if (kt >= 2 * qb) {
            #pragma unroll
            for (int j = 0; j < 8; j++) {
                int cg = (kt << 6) + 8 * j + 2 * col;
                if (cg     > rg0) sf[j][0] = -1e30f;
                if (cg + 1 > rg0) sf[j][1] = -1e30f;
                if (cg     > rg1) sf[j][2] = -1e30f;
                if (cg + 1 > rg1) sf[j][3] = -1e30f;
            }
        }

        float mx0 = -1e30f, mx1 = -1e30f;
        #pragma unroll
        for (int j = 0; j < 8; j++) {
            mx0 = fmaxf(mx0, fmaxf(sf[j][0], sf[j][1]));
            mx1 = fmaxf(mx1, fmaxf(sf[j][2], sf[j][3]));
        }
        mx0 = fmaxf(mx0, __shfl_xor_sync(0xffffffffu, mx0, 1));
        mx0 = fmaxf(mx0, __shfl_xor_sync(0xffffffffu, mx0, 2));
        mx1 = fmaxf(mx1, __shfl_xor_sync(0xffffffffu, mx1, 1));
        mx1 = fmaxf(mx1, __shfl_xor_sync(0xffffffffu, mx1, 2));
        float mn0 = fmaxf(m0v, mx0), mn1 = fmaxf(m1v, mx1);
        float corr0 = __expf(m0v - mn0), corr1 = __expf(m1v - mn1);
        float rs0 = 0.f, rs1 = 0.f;
        #pragma unroll
        for (int j = 0; j < 8; j++) {
            float p0 = __expf(sf[j][0] - mn0);
            float p1 = __expf(sf[j][1] - mn0);
            float p2 = __expf(sf[j][2] - mn1);
            float p3 = __expf(sf[j][3] - mn1);
            Ps[(r0+row)*68 + 8*j + 2*col]       = p0;
            Ps[(r0+row)*68 + 8*j + 2*col + 1]   = p1;
            Ps[(r0+row+8)*68 + 8*j + 2*col]     = p2;
            Ps[(r0+row+8)*68 + 8*j + 2*col + 1] = p3;
            rs0 += p0 + p1; rs1 += p2 + p3;
        }
        rs0 += __shfl_xor_sync(0xffffffffu, rs0, 1);
        rs0 += __shfl_xor_sync(0xffffffffu, rs0, 2);
        rs1 += __shfl_xor_sync(0xffffffffu, rs1, 1);
        rs1 += __shfl_xor_sync(0xffffffffu, rs1, 2);
        l0 = l0 * corr0 + rs0;  l1 = l1 * corr1 + rs1;
        m0v = mn0; m1v = mn1;
        #pragma unroll
        for (int nf = 0; nf < 16; nf++) {
            o[nf][0] *= corr0; o[nf][1] *= corr0;
            o[nf][2] *= corr1; o[nf][3] *= corr1;
        }
        __syncwarp();

        // ---- O += P V : tf32 3-pass (V natural layout) ----
        #pragma unroll
        for (int k8 = 0; k8 < 8; k8++) {
            const int kb = k8 << 3;
            float p0 = Ps[(r0+row)*68 + kb + col],     p1 = Ps[(r0+row+8)*68 + kb + col];
            float p2 = Ps[(r0+row)*68 + kb + col + 4], p3 = Ps[(r0+row+8)*68 + kb + col + 4];
            float ph0 = tf32_hi(p0), ph1 = tf32_hi(p1), ph2 = tf32_hi(p2), ph3 = tf32_hi(p3);
            uint32_t ah0 = f2b(ph0), ah1 = f2b(ph1), ah2 = f2b(ph2), ah3 = f2b(ph3);
            uint32_t al0 = f2b(p0-ph0), al1 = f2b(p1-ph1), al2 = f2b(p2-ph2), al3 = f2b(p3-ph3);
            #pragma unroll
            for (int nf = 0; nf < 16; nf++) {
                float v0 = Vs[(kb+col)*132 + 8*nf + row], v1 = Vs[(kb+col+4)*132 + 8*nf + row];
                float h0 = tf32_hi(v0), h1 = tf32_hi(v1);
                uint32_t bh0 = f2b(h0), bh1 = f2b(h1);
                uint32_t bl0 = f2b(v0-h0), bl1 = f2b(v1-h1);
                MMA_TF32(o[nf], ah0, ah1, ah2, ah3, bh0, bh1);
                MMA_TF32(o[nf], al0, al1, al2, al3, bh0, bh1);
                MMA_TF32(o[nf], ah0, ah1, ah2, ah3, bl0, bl1);
            }
        }
    }

    const float inv0 = 1.f / l0, inv1 = 1.f / l1;
    float* Op0 = O + (size_t)(b * SEQ + qb * 128 + r0 + row) * DIM + h * HDIM;
    float* Op1 = Op0 + 8 * DIM;
    #pragma unroll
    for (int nf = 0; nf < 16; nf++) {
        int cc = 8 * nf + 2 * col;
        *(float2*)(Op0 + cc) = make_float2(o[nf][0] * inv0, o[nf][1] * inv0);
        *(float2*)(Op1 + cc) = make_float2(o[nf][2] * inv1, o[nf][3] * inv1);
    }
}

// =====================================================================
// memories [M,D,E] fp32 -> bt [E][m*D+d] bf16
// =====================================================================
__global__ void transpose_mem(const float* __restrict__ mem, __nv_bfloat16* __restrict__ bt)
{
    __shared__ float t[32][33];
    const int m = blockIdx.z;
    const int d0 = blockIdx.x << 5, e0 = blockIdx.y << 5;
    const float* src = mem + ((size_t)m * DIM + d0) * DIM + e0;
    for (int i = threadIdx.y; i < 32; i += 8)
        t[i][threadIdx.x] = src[(size_t)i * DIM + threadIdx.x];
    __syncthreads();
    __nv_bfloat16* dst = bt + (size_t)e0 * KTOT + m * DIM + d0;
    for (int i = threadIdx.y; i < 32; i += 8)
        dst[(size_t)i * KTOT + threadIdx.x] = __float2bfloat16_rn(t[threadIdx.x][i]);
}

// as[r][m*2048+d] = bf16(csc[m][r] * sigma[r][d])
__global__ void __launch_bounds__(256) prescale_kernel(
    const float* __restrict__ sig, const float* __restrict__ csc,
    __nv_bfloat16* __restrict__ as)
{
    const int r = blockIdx.x;
    float cm[NMEM];
    #pragma unroll
    for (int m = 0; m < NMEM; m++) cm[m] = csc[m * NROWS + r];
    const float* sp = sig + (size_t)r * DIM;
    __nv_bfloat16* ap = as + (size_t)r * KTOT;
    for (int d = threadIdx.x * 4; d < DIM; d += 1024) {
        float4 s = *(const float4*)(sp + d);
        #pragma unroll
        for (int m = 0; m < NMEM; m++) {
            __nv_bfloat162 p0 = __floats2bfloat162_rn(s.x * cm[m], s.y * cm[m]);
            __nv_bfloat162 p1 = __floats2bfloat162_rn(s.z * cm[m], s.w * cm[m]);
            *(__nv_bfloat162*)(ap + m * DIM + d)     = p0;
            *(__nv_bfloat162*)(ap + m * DIM + d + 2) = p1;
        }
    }
}

// =====================================================================
// sigma / raw / rel / cscale / blend
// =====================================================================
__inline__ __device__ float warpReduceSum(float v) {
    #pragma unroll
    for (int o = 16; o > 0; o >>= 1) v += __shfl_down_sync(0xffffffffu, v, o);
    return v;
}

__global__ void __launch_bounds__(256) sigma_raw_kernel(
    const float* __restrict__ q, const float* __restrict__ norms,
    float* __restrict__ sig, float* __restrict__ raw)
{
    const int r = blockIdx.x;
    const int base = r * DIM;
    float a[NMEM] = {0.f, 0.f, 0.f, 0.f};
    for (int c = threadIdx.x * 4; c < DIM; c += 1024) {
        float4 qv = *(const float4*)(q + base + c);
        float4 s;
        s.x = qv.x > 0.f ? qv.x + 1.f : __expf(qv.x);
        s.y = qv.y > 0.f ? qv.y + 1.f : __expf(qv.y);
        s.z = qv.z > 0.f ? qv.z + 1.f : __expf(qv.z);
        s.w = qv.w > 0.f ? qv.w + 1.f : __expf(qv.w);
        *(float4*)(sig + base + c) = s;
        #pragma unroll
        for (int m = 0; m < NMEM; m++) {
            float4 nv = *(const float4*)(norms + m * DIM + c);
            a[m] += s.x * nv.x + s.y * nv.y + s.z * nv.z + s.w * nv.w;
        }
    }
    __shared__ float red[NMEM][8];
    const int lane = threadIdx.x & 31, wid = threadIdx.x >> 5;
    #pragma unroll
    for (int m = 0; m < NMEM; m++) a[m] = warpReduceSum(a[m]);
    if (lane == 0)
        #pragma unroll
        for (int m = 0; m < NMEM; m++) red[m][wid] = a[m];
    __syncthreads();
    if (wid == 0) {
        #pragma unroll
        for (int m = 0; m < NMEM; m++) {
            float v = (lane < 8) ? red[m][lane] : 0.f;
            v = warpReduceSum(v);
            if (lane == 0) raw[m * NROWS + r] = v;
        }
    }
}

__global__ void __launch_bounds__(256) rel_kernel(
    const float* __restrict__ raw, float* __restrict__ rel)
{
    const int m = blockIdx.x >> 1, b = blockIdx.x & 1;
    float acc = 0.f;
    for (int s = threadIdx.x; s < SEQ; s += 256) acc += raw[m * NROWS + b * SEQ + s];
    __shared__ float red[8];
    const int lane = threadIdx.x & 31, wid = threadIdx.x >> 5;
    acc = warpReduceSum(acc);
    if (lane == 0) red[wid] = acc;
    __syncthreads();
    if (threadIdx.x == 0) {
        float t = 0.f;
        #pragma unroll
        for (int w = 0; w < 8; w++) t += red[w];
        rel[m * BATCH + b] = t / (float)SEQ;
    }
}

__global__ void __launch_bounds__(256) cscale_kernel(
    const float* __restrict__ raw, const float* __restrict__ rel,
    float* __restrict__ csc)
{
    const int r = blockIdx.x * 256 + threadIdx.x;
    if (r >= NROWS) return;
    const int b = r >> 11;
    float e[NMEM];
    #pragma unroll
    for (int m = 0; m < NMEM; m++) e[m] = rel[m * BATCH + b];
    float mx = fmaxf(fmaxf(e[0], e[1]), fmaxf(e[2], e[3]));
    float w[NMEM], sum = 0.f;
    #pragma unroll
    for (int m = 0; m < NMEM; m++) { w[m] = __expf(e[m] - mx); sum += w[m]; }
    const float inv = 1.f / sum;
    #pragma unroll
    for (int m = 0; m < NMEM; m++)
        csc[m * NROWS + r] = w[m] * inv / fmaxf(raw[m * NROWS + r], 1e-6f);
}

__global__ void __launch_bounds__(256) blend_kernel(
    const float* __restrict__ mem, const float* __restrict__ loc,
    const float* __restrict__ gate, float* __restrict__ bl)
{
    const int i = blockIdx.x * 256 + threadIdx.x;
    const float g = 1.f / (1.f + __expf(-gate[0]));
    const float gi = 1.f - g;
    float4 m = ((const float4*)mem)[i], l = ((const float4*)loc)[i];
    ((float4*)bl)[i] = make_float4(g*m.x + gi*l.x, g*m.y + gi*l.y,
                                   g*m.z + gi*l.z, g*m.w + gi*l.w);
}

// =====================================================================
extern "C" void kernel_launch(void* const* d_in, const int* in_sizes, int n_in,
                              void* d_out, int out_size)
{
    const float* x        = (const float*)d_in[0];
    const float* w_q      = (const float*)d_in[1];
    const float* w_k      = (const float*)d_in[2];
    const float* w_v      = (const float*)d_in[3];
    const float* w_o      = (const float*)d_in[4];
    const float* gate     = (const float*)d_in[5];
    const float* memories = (const float*)d_in[6];
    const float* mnorms   = (const float*)d_in[7];
    float* out = (float*)d_out;

    float *q, *k, *v, *sig, *memo, *loc, *raw, *rel, *csc;
    __nv_bfloat16 *bt, *as;
    cudaGetSymbolAddress((void**)&q,    g_q);
    cudaGetSymbolAddress((void**)&k,    g_k);
    cudaGetSymbolAddress((void**)&v,    g_v);
    cudaGetSymbolAddress((void**)&sig,  g_sig);
    cudaGetSymbolAddress((void**)&memo, g_mem);
    cudaGetSymbolAddress((void**)&loc,  g_loc);
    cudaGetSymbolAddress((void**)&bt,   g_bt);
    cudaGetSymbolAddress((void**)&as,   g_as);
    cudaGetSymbolAddress((void**)&raw,  g_raw);
    cudaGetSymbolAddress((void**)&rel,  g_rel);
    cudaGetSymbolAddress((void**)&csc,  g_csc);

    cudaFuncSetAttribute(gemm_h2,     cudaFuncAttributeMaxDynamicSharedMemorySize, SMEM_H2);
    cudaFuncSetAttribute(gemm_mem_bf, cudaFuncAttributeMaxDynamicSharedMemorySize, SMEM_MB);
    cudaFuncSetAttribute(flash_mma,   cudaFuncAttributeMaxDynamicSharedMemorySize, FLASH_SMEM);

    dim3 gg(DIM / 128, NROWS / 128);          // (16, 32)
    dim3 gg3(DIM / 128, NROWS / 128, 3);

    transpose_mem<<<dim3(DIM / 32, DIM / 32, NMEM), dim3(32, 8)>>>(memories, bt);

    // fused Q/K/V projections
    gemm_h2<<<gg3, 512, SMEM_H2>>>(x, w_q, w_k, w_v, q, k, v, NROWS, DIM, DIM);

    sigma_raw_kernel<<<NROWS, 256>>>(q, mnorms, sig, raw);
    rel_kernel<<<NMEM * BATCH, 256>>>(raw, rel);
    cscale_kernel<<<NROWS / 256, 256>>>(raw, rel, csc);
    prescale_kernel<<<NROWS, 256>>>(sig, csc, as);

    gemm_mem_bf<<<gg, 512, SMEM_MB>>>(as, bt, memo);

    flash_mma<<<dim3(SEQ / 128, BATCH * NHEADS), 256, FLASH_SMEM>>>(q, k, v, loc);

    blend_kernel<<<NROWS * DIM / 4 / 256, 256>>>(memo, loc, gate, sig);

    gemm_h2<<<dim3(DIM / 128, NROWS / 128, 1), 512, SMEM_H2>>>(
        sig, w_o, w_o, w_o, out, out, out, NROWS, DIM, DIM);
}